// round 5
// baseline (speedup 1.0000x reference)
#include <cuda_runtime.h>
#include <math.h>

// Problem constants (B=1, D=16, H=64, W=64)
#define NTOK   65536
#define CDIM   192
#define NHEADS 6
#define HD     32
#define NWIN   256
#define NT     256
#define HIDDEN 768
#define RANK1  384
#define RANK2  96
#define ATTN_SCALE 0.17677669529663687f  // 32^-0.5

// ---------------- scratch (device globals; no runtime allocation) ----------------
__device__ float g_tok192a[(size_t)NTOK * CDIM];
__device__ float g_qkv[(size_t)NTOK * 576];
__device__ float g_attn[(size_t)NTOK * CDIM];
__device__ float g_x1[(size_t)NTOK * CDIM];
__device__ float g_r1[(size_t)NTOK * RANK1];
__device__ float g_hid[(size_t)NTOK * HIDDEN];
__device__ float g_conv[(size_t)NTOK * HIDDEN];
__device__ float g_r2[(size_t)NTOK * RANK2];

// ---------------- helpers ----------------
__device__ __forceinline__ int token_to_wrow(int n) {
    int w = n & 63, h = (n >> 6) & 63, d = n >> 12;
    int win = ((d >> 2) << 6) | ((h >> 3) << 3) | (w >> 3);
    int t   = ((d & 3) << 6) | ((h & 7) << 3) | (w & 7);
    return (win << 8) | t;
}
__device__ __forceinline__ int wrow_to_token(int r) {
    int win = r >> 8, t = r & 255;
    int d = ((win >> 6) << 2) | (t >> 6);
    int h = (((win >> 3) & 7) << 3) | ((t >> 3) & 7);
    int w = ((win & 7) << 3) | (t & 7);
    return (d << 12) | (h << 6) | w;
}
__device__ __forceinline__ void cp16(void* smem, const void* gmem) {
    unsigned s = (unsigned)__cvta_generic_to_shared(smem);
    asm volatile("cp.async.cg.shared.global [%0], [%1], 16;\n" :: "r"(s), "l"(gmem));
}
__device__ __forceinline__ void cp16z(void* smem, const void* gmem) {
    unsigned s = (unsigned)__cvta_generic_to_shared(smem);
    asm volatile("cp.async.cg.shared.global [%0], [%1], 16, 0;\n" :: "r"(s), "l"(gmem));
}
__device__ __forceinline__ unsigned f2tf(float f) {
    unsigned u;
    asm("cvt.rna.tf32.f32 %0, %1;" : "=r"(u) : "f"(f));
    return u;
}
__device__ __forceinline__ float f2tf_val(float f) {
    return __uint_as_float(f2tf(f));
}
#define MMA_TF32(C, A, B)                                                      \
    asm volatile(                                                              \
        "mma.sync.aligned.m16n8k8.row.col.f32.tf32.tf32.f32 "                  \
        "{%0,%1,%2,%3},{%4,%5,%6,%7},{%8,%9},{%0,%1,%2,%3};\n"                 \
        : "+f"((C)[0]), "+f"((C)[1]), "+f"((C)[2]), "+f"((C)[3])               \
        : "r"((A)[0]), "r"((A)[1]), "r"((A)[2]), "r"((A)[3]),                  \
          "r"((B)[0]), "r"((B)[1]))

// ---------------- LayerNorm: warp per token, 8 tokens per block ----------------
template <bool PERM>
__global__ void __launch_bounds__(256)
ln_kernel(const float* __restrict__ x, const float* __restrict__ g,
          const float* __restrict__ b, float* __restrict__ out) {
    int lane = threadIdx.x & 31, wid = threadIdx.x >> 5;
    int n = (blockIdx.x << 3) + wid;
    const float* xp = x + (size_t)n * CDIM;
    float v[6];
#pragma unroll
    for (int i = 0; i < 6; i++) v[i] = xp[lane + (i << 5)];
    float s = 0.f, s2 = 0.f;
#pragma unroll
    for (int i = 0; i < 6; i++) { s += v[i]; s2 += v[i] * v[i]; }
#pragma unroll
    for (int o = 16; o; o >>= 1) {
        s  += __shfl_xor_sync(0xffffffffu, s,  o);
        s2 += __shfl_xor_sync(0xffffffffu, s2, o);
    }
    float mean = s * (1.0f / CDIM);
    float rstd = rsqrtf(s2 * (1.0f / CDIM) - mean * mean + 1e-5f);
    int orow = PERM ? token_to_wrow(n) : n;
    float* op = out + (size_t)orow * CDIM;
#pragma unroll
    for (int i = 0; i < 6; i++) {
        int c = lane + (i << 5);
        op[c] = (v[i] - mean) * rstd * __ldg(g + c) + __ldg(b + c);
    }
}

// ---------------- TF32 tensor-core GEMM 128x128x32, 2-stage, one sync/iter ---------
// MODE 0: C=A*B  1: +bias  2: +bias+resid w/ inverse window permute  3: +bias+resid
template <int MODE>
__global__ void __launch_bounds__(256, 2)
mma_gemm(const float* __restrict__ A, const float* __restrict__ B,
         const float* __restrict__ bias, const float* __restrict__ resid,
         float* __restrict__ C, int N, int K) {
    __shared__ float As[2][128][36];   // [stage][m][k]  (pad 36 -> conflict-free)
    __shared__ float Bs[2][32][136];   // [stage][k][n]  (pad 136 -> conflict-free)
    int tid = threadIdx.x, lane = tid & 31, warp = tid >> 5;
    int wm = warp & 1, wn = warp >> 1;
    int bm = blockIdx.y << 7, bn = blockIdx.x << 7;
    int q = lane & 3, g8 = lane >> 2;

    float c[4][4][4];
#pragma unroll
    for (int mt = 0; mt < 4; mt++)
#pragma unroll
        for (int nt = 0; nt < 4; nt++)
#pragma unroll
            for (int r = 0; r < 4; r++) c[mt][nt][r] = 0.f;

    int KT = K >> 5;

#define COPY_STAGE(S, K0)                                                        \
    do {                                                                         \
        _Pragma("unroll")                                                        \
        for (int cc = 0; cc < 4; cc++) {                                         \
            int id = tid + (cc << 8);                                            \
            int r = id >> 3, kq = (id & 7) << 2;                                 \
            cp16(&As[S][r][kq], A + (size_t)(bm + r) * K + (K0) + kq);           \
        }                                                                        \
        _Pragma("unroll")                                                        \
        for (int cc = 0; cc < 4; cc++) {                                         \
            int id = tid + (cc << 8);                                            \
            int r = id >> 5, col = (id & 31) << 2;                               \
            int gn = bn + col;                                                   \
            const float* bp = B + (size_t)((K0) + r) * N + gn;                   \
            if (gn + 4 <= N) cp16(&Bs[S][r][col], bp);                           \
            else             cp16z(&Bs[S][r][col], B);                           \
        }                                                                        \
    } while (0)

    COPY_STAGE(0, 0);
    asm volatile("cp.async.commit_group;\n");

    for (int kt = 0; kt < KT; kt++) {
        asm volatile("cp.async.wait_group 0;\n");
        __syncthreads();
        if (kt + 1 < KT) {
            COPY_STAGE((kt + 1) & 1, (kt + 1) << 5);
            asm volatile("cp.async.commit_group;\n");
        }
        int s = kt & 1;
#pragma unroll
        for (int kk = 0; kk < 32; kk += 8) {
            unsigned af[4][4], bf[4][2];
#pragma unroll
            for (int mt = 0; mt < 4; mt++) {
                int m = wm * 64 + mt * 16 + g8;
                af[mt][0] = __float_as_uint(As[s][m][kk + q]);
                af[mt][1] = __float_as_uint(As[s][m + 8][kk + q]);
                af[mt][2] = __float_as_uint(As[s][m][kk + q + 4]);
                af[mt][3] = __float_as_uint(As[s][m + 8][kk + q + 4]);
            }
#pragma unroll
            for (int nt = 0; nt < 4; nt++) {
                int n = wn * 32 + nt * 8 + g8;
                bf[nt][0] = __float_as_uint(Bs[s][kk + q][n]);
                bf[nt][1] = __float_as_uint(Bs[s][kk + q + 4][n]);
            }
#pragma unroll
            for (int mt = 0; mt < 4; mt++)
#pragma unroll
                for (int nt = 0; nt < 4; nt++)
                    MMA_TF32(c[mt][nt], af[mt], bf[nt]);
        }
    }
#undef COPY_STAGE

#pragma unroll
    for (int mt = 0; mt < 4; mt++) {
        int row0 = bm + wm * 64 + mt * 16 + g8;
#pragma unroll
        for (int half = 0; half < 2; half++) {
            int row = row0 + half * 8;
            int orow = (MODE == 2) ? wrow_to_token(row) : row;
#pragma unroll
            for (int nt = 0; nt < 4; nt++) {
                int col = bn + wn * 32 + nt * 8 + (q << 1);
                if (col < N) {
                    float v0 = c[mt][nt][half * 2 + 0];
                    float v1 = c[mt][nt][half * 2 + 1];
                    if (MODE >= 1) { v0 += bias[col]; v1 += bias[col + 1]; }
                    if (MODE >= 2) {
                        float2 rr = *(const float2*)(resid + (size_t)orow * N + col);
                        v0 += rr.x; v1 += rr.y;
                    }
                    *(float2*)(C + (size_t)orow * N + col) = make_float2(v0, v1);
                }
            }
        }
    }
}

// ---------------- tensor-core windowed attention: one block per (head, window) ------
#define ATTN_SM_FLOATS (9216 + 8320 + 9216 + 1576 + 256)
__global__ void __launch_bounds__(256)
attn_mma_kernel(const float* __restrict__ qkv, const float* __restrict__ rel_bias,
                float* __restrict__ out) {
    extern __shared__ float sm[];
    float* Ks  = sm;            // [256][36]
    float* Vt  = sm + 9216;     // [32][260]
    float* Ps  = sm + 17536;    // [256][36]  (Q staging, then P)
    float* bsh = sm + 26752;    // [1575]
    int*   sid = (int*)(sm + 28328);

    int head = blockIdx.x, win = blockIdx.y;
    int tid = threadIdx.x, lane = tid & 31, warp = tid >> 5;
    int q = lane & 3, g8 = lane >> 2;
    int m0 = warp << 5;

    const float* base = qkv + (size_t)win * 256 * 576 + head * HD;
    for (int idx = tid; idx < 256 * 32; idx += 256) {
        int r = idx >> 5, d = idx & 31;
        const float* p = base + (size_t)r * 576 + d;
        Ks[r * 36 + d]  = f2tf_val(p[192]);
        Vt[d * 260 + r] = f2tf_val(p[384]);
    }
#pragma unroll 4
    for (int i = 0; i < 32; i++)
        Ps[(m0 + i) * 36 + lane] = base[(size_t)(m0 + i) * 576 + lane];
    for (int i = tid; i < 1575; i += 256) bsh[i] = rel_bias[i * 6 + head];
    {
        int t = tid;
        int gd = ((win >> 6) << 2) | (t >> 6);
        int gh = (((win >> 3) & 7) << 3) | ((t >> 3) & 7);
        int gw = ((win & 7) << 3) | (t & 7);
        sid[t] = ((((gd + 2) & 15) >> 2) << 6) | ((((gh + 4) & 63) >> 3) << 3) |
                 (((gw + 4) & 63) >> 3);
    }
    __syncthreads();

    unsigned qf[2][4][4];
#pragma unroll
    for (int mt = 0; mt < 2; mt++)
#pragma unroll
        for (int kk = 0; kk < 4; kk++) {
            int m = m0 + mt * 16 + g8, k = kk * 8 + q;
            qf[mt][kk][0] = f2tf(Ps[m * 36 + k] * ATTN_SCALE);
            qf[mt][kk][1] = f2tf(Ps[(m + 8) * 36 + k] * ATTN_SCALE);
            qf[mt][kk][2] = f2tf(Ps[m * 36 + k + 4] * ATTN_SCALE);
            qf[mt][kk][3] = f2tf(Ps[(m + 8) * 36 + k + 4] * ATTN_SCALE);
        }
    int rd_[2][2], rh_[2][2], rw_[2][2], msid[2][2];
#pragma unroll
    for (int mt = 0; mt < 2; mt++)
#pragma unroll
        for (int h = 0; h < 2; h++) {
            int r = m0 + mt * 16 + h * 8 + g8;
            rd_[mt][h] = r >> 6; rh_[mt][h] = (r >> 3) & 7; rw_[mt][h] = r & 7;
            msid[mt][h] = sid[r];
        }
    __syncwarp();

    float o[2][4][4];
#pragma unroll
    for (int mt = 0; mt < 2; mt++)
#pragma unroll
        for (int nt = 0; nt < 4; nt++)
#pragma unroll
            for (int e = 0; e < 4; e++) o[mt][nt][e] = 0.f;
    float rs[2][2] = {{0.f, 0.f}, {0.f, 0.f}};

    for (int ck = 0; ck < 256; ck += 32) {
        float s[2][4][4];
#pragma unroll
        for (int mt = 0; mt < 2; mt++)
#pragma unroll
            for (int nt = 0; nt < 4; nt++)
#pragma unroll
                for (int e = 0; e < 4; e++) s[mt][nt][e] = 0.f;
#pragma unroll
        for (int kk = 0; kk < 4; kk++) {
            unsigned kf[4][2];
#pragma unroll
            for (int nt = 0; nt < 4; nt++) {
                int n = ck + nt * 8 + g8;
                kf[nt][0] = __float_as_uint(Ks[n * 36 + kk * 8 + q]);
                kf[nt][1] = __float_as_uint(Ks[n * 36 + kk * 8 + q + 4]);
            }
#pragma unroll
            for (int mt = 0; mt < 2; mt++)
#pragma unroll
                for (int nt = 0; nt < 4; nt++)
                    MMA_TF32(s[mt][nt], qf[mt][kk], kf[nt]);
        }
#pragma unroll
        for (int nt = 0; nt < 4; nt++) {
            int cc = ck + nt * 8;
            int cd = cc >> 6, ch = (cc >> 3) & 7;
            int sc = (q >= 2) ? sid[cc + 4] : sid[cc];
#pragma unroll
            for (int mt = 0; mt < 2; mt++)
#pragma unroll
                for (int h = 0; h < 2; h++) {
                    int bidx = (rd_[mt][h] - cd + 3) * 225 +
                               (rh_[mt][h] - ch + 7) * 15 + rw_[mt][h] + 7 - (q << 1);
                    float p0, p1;
                    if (msid[mt][h] == sc) {
                        p0 = __expf(s[mt][nt][h * 2 + 0] + bsh[bidx]);
                        p1 = __expf(s[mt][nt][h * 2 + 1] + bsh[bidx - 1]);
                    } else { p0 = 0.f; p1 = 0.f; }
                    rs[mt][h] += p0 + p1;
                    int r = m0 + mt * 16 + h * 8 + g8;
                    *(float2*)&Ps[r * 36 + nt * 8 + (q << 1)] =
                        make_float2(f2tf_val(p0), f2tf_val(p1));
                }
        }
        __syncwarp();
#pragma unroll
        for (int kk = 0; kk < 4; kk++) {
            unsigned vf[4][2], pf[2][4];
#pragma unroll
            for (int nto = 0; nto < 4; nto++) {
                int d = nto * 8 + g8;
                vf[nto][0] = __float_as_uint(Vt[d * 260 + ck + kk * 8 + q]);
                vf[nto][1] = __float_as_uint(Vt[d * 260 + ck + kk * 8 + q + 4]);
            }
#pragma unroll
            for (int mt = 0; mt < 2; mt++) {
                int m = m0 + mt * 16 + g8, k = kk * 8 + q;
                pf[mt][0] = __float_as_uint(Ps[m * 36 + k]);
                pf[mt][1] = __float_as_uint(Ps[(m + 8) * 36 + k]);
                pf[mt][2] = __float_as_uint(Ps[m * 36 + k + 4]);
                pf[mt][3] = __float_as_uint(Ps[(m + 8) * 36 + k + 4]);
            }
#pragma unroll
            for (int mt = 0; mt < 2; mt++)
#pragma unroll
                for (int nto = 0; nto < 4; nto++)
                    MMA_TF32(o[mt][nto], pf[mt], vf[nto]);
        }
        __syncwarp();
    }

#pragma unroll
    for (int mt = 0; mt < 2; mt++)
#pragma unroll
        for (int h = 0; h < 2; h++) {
            float v = rs[mt][h];
            v += __shfl_xor_sync(0xffffffffu, v, 1);
            v += __shfl_xor_sync(0xffffffffu, v, 2);
            rs[mt][h] = 1.f / v;
        }
#pragma unroll
    for (int mt = 0; mt < 2; mt++)
#pragma unroll
        for (int h = 0; h < 2; h++) {
            int r = m0 + mt * 16 + h * 8 + g8;
            float* op = out + (size_t)(win * 256 + r) * CDIM + head * HD;
            float inv = rs[mt][h];
#pragma unroll
            for (int nto = 0; nto < 4; nto++)
                *(float2*)(op + nto * 8 + (q << 1)) =
                    make_float2(o[mt][nto][h * 2 + 0] * inv,
                                o[mt][nto][h * 2 + 1] * inv);
        }
}

// ---------------- depthwise 3x3x3 conv + bias + exact GELU ----------------
__global__ void __launch_bounds__(256)
conv_gelu_kernel(const float* __restrict__ hin, const float* __restrict__ wt,
                 const float* __restrict__ cb, float* __restrict__ hout) {
    int n = blockIdx.x;
    int d = n >> 12, h = (n >> 6) & 63, wx = n & 63;
    int tid = threadIdx.x;
#pragma unroll
    for (int jj = 0; jj < 3; jj++) {
        int c = tid + jj * 256;
        float acc = cb[c];
        const float* wc = wt + c * 27;
        int k = 0;
#pragma unroll
        for (int kd = -1; kd <= 1; kd++) {
            int dd = d + kd;
#pragma unroll
            for (int kh = -1; kh <= 1; kh++) {
                int hh = h + kh;
#pragma unroll
                for (int kw = -1; kw <= 1; kw++, k++) {
                    int ww = wx + kw;
                    if ((unsigned)dd < 16u && (unsigned)hh < 64u && (unsigned)ww < 64u) {
                        int nb = (dd << 12) | (hh << 6) | ww;
                        acc += wc[k] * hin[(size_t)nb * HIDDEN + c];
                    }
                }
            }
        }
        float gl = 0.5f * acc * (1.f + erff(acc * 0.70710678118654752f));
        hout[(size_t)n * HIDDEN + c] = gl;
    }
}

// ---------------- launch ----------------
extern "C" void kernel_launch(void* const* d_in, const int* in_sizes, int n_in,
                              void* d_out, int out_size) {
    const float* x     = (const float*)d_in[0];
    const float* n1g   = (const float*)d_in[1];
    const float* n1b   = (const float*)d_in[2];
    const float* qkvw  = (const float*)d_in[3];
    const float* qkvb  = (const float*)d_in[4];
    const float* relb  = (const float*)d_in[5];
    const float* projw = (const float*)d_in[6];
    const float* projb = (const float*)d_in[7];
    const float* n2g   = (const float*)d_in[8];
    const float* n2b   = (const float*)d_in[9];
    const float* fc1A  = (const float*)d_in[10];
    const float* fc1Bw = (const float*)d_in[11];
    const float* fc1Bb = (const float*)d_in[12];
    const float* dww   = (const float*)d_in[13];
    const float* dwb   = (const float*)d_in[14];
    const float* fc2A  = (const float*)d_in[15];
    const float* fc2Bw = (const float*)d_in[16];
    const float* fc2Bb = (const float*)d_in[17];
    float* out = (float*)d_out;

    float *p_tok, *p_qkv, *p_attn, *p_x1, *p_r1, *p_hid, *p_conv, *p_r2;
    cudaGetSymbolAddress((void**)&p_tok,  g_tok192a);
    cudaGetSymbolAddress((void**)&p_qkv,  g_qkv);
    cudaGetSymbolAddress((void**)&p_attn, g_attn);
    cudaGetSymbolAddress((void**)&p_x1,   g_x1);
    cudaGetSymbolAddress((void**)&p_r1,   g_r1);
    cudaGetSymbolAddress((void**)&p_hid,  g_hid);
    cudaGetSymbolAddress((void**)&p_conv, g_conv);
    cudaGetSymbolAddress((void**)&p_r2,   g_r2);

    const int ATTN_SMEM = ATTN_SM_FLOATS * 4;
    cudaFuncSetAttribute(attn_mma_kernel, cudaFuncAttributeMaxDynamicSharedMemorySize, ATTN_SMEM);

    // 1. LN1 + window permute
    ln_kernel<true><<<NTOK / 8, 256>>>(x, n1g, n1b, p_tok);
    // 2. qkv = xw @ qkv_w + b   [65536 x 576], K=192
    mma_gemm<1><<<dim3(5, 512), 256>>>(p_tok, qkvw, qkvb, nullptr, p_qkv, 576, 192);
    // 3. windowed attention (tensor-core)
    attn_mma_kernel<<<dim3(NHEADS, NWIN), 256, ATTN_SMEM>>>(p_qkv, relb, p_attn);
    // 4. proj + inverse permute + residual -> x1 (token order)
    mma_gemm<2><<<dim3(2, 512), 256>>>(p_attn, projw, projb, x, p_x1, 192, 192);
    // 5. LN2
    ln_kernel<false><<<NTOK / 8, 256>>>(p_x1, n2g, n2b, p_tok);
    // 6. r1 = hn @ fc1_A   [65536 x 384], K=192
    mma_gemm<0><<<dim3(3, 512), 256>>>(p_tok, fc1A, nullptr, nullptr, p_r1, 384, 192);
    // 7. hid = r1 @ fc1_Bw + b   [65536 x 768], K=384
    mma_gemm<1><<<dim3(6, 512), 256>>>(p_r1, fc1Bw, fc1Bb, nullptr, p_hid, 768, 384);
    // 8. depthwise conv3d + bias + GELU
    conv_gelu_kernel<<<NTOK, 256>>>(p_hid, dww, dwb, p_conv);
    // 9. r2 = conv @ fc2_A   [65536 x 96], K=768
    mma_gemm<0><<<dim3(1, 512), 256>>>(p_conv, fc2A, nullptr, nullptr, p_r2, 96, 768);
    // 10. out = x1 + r2 @ fc2_Bw + b   [65536 x 192], K=96
    mma_gemm<3><<<dim3(2, 512), 256>>>(p_r2, fc2Bw, fc2Bb, p_x1, out, 192, 96);
}

// round 6
// speedup vs baseline: 1.4941x; 1.4941x over previous
#include <cuda_runtime.h>
#include <math.h>

// Problem constants (B=1, D=16, H=64, W=64)
#define NTOK   65536
#define CDIM   192
#define NHEADS 6
#define HD     32
#define NWIN   256
#define NT     256
#define HIDDEN 768
#define RANK1  384
#define RANK2  96
#define ATTN_SCALE 0.17677669529663687f  // 32^-0.5

// ---------------- scratch (device globals; no runtime allocation) ----------------
__device__ float g_tok192a[(size_t)NTOK * CDIM];
__device__ float g_qkv[(size_t)NTOK * 576];
__device__ float g_attn[(size_t)NTOK * CDIM];
__device__ float g_x1[(size_t)NTOK * CDIM];
__device__ float g_r1[(size_t)NTOK * RANK1];
__device__ float g_hid[(size_t)NTOK * HIDDEN];
__device__ float g_conv[(size_t)NTOK * HIDDEN];
__device__ float g_r2[(size_t)NTOK * RANK2];

// ---------------- helpers ----------------
__device__ __forceinline__ int token_to_wrow(int n) {
    int w = n & 63, h = (n >> 6) & 63, d = n >> 12;
    int win = ((d >> 2) << 6) | ((h >> 3) << 3) | (w >> 3);
    int t   = ((d & 3) << 6) | ((h & 7) << 3) | (w & 7);
    return (win << 8) | t;
}
__device__ __forceinline__ int wrow_to_token(int r) {
    int win = r >> 8, t = r & 255;
    int d = ((win >> 6) << 2) | (t >> 6);
    int h = (((win >> 3) & 7) << 3) | ((t >> 3) & 7);
    int w = ((win & 7) << 3) | (t & 7);
    return (d << 12) | (h << 6) | w;
}
__device__ __forceinline__ void cp16(void* smem, const void* gmem) {
    unsigned s = (unsigned)__cvta_generic_to_shared(smem);
    asm volatile("cp.async.cg.shared.global [%0], [%1], 16;\n" :: "r"(s), "l"(gmem));
}
__device__ __forceinline__ void cp16z(void* smem, const void* gmem) {
    unsigned s = (unsigned)__cvta_generic_to_shared(smem);
    asm volatile("cp.async.cg.shared.global [%0], [%1], 16, 0;\n" :: "r"(s), "l"(gmem));
}
__device__ __forceinline__ unsigned f2tf(float f) {
    unsigned u;
    asm("cvt.rna.tf32.f32 %0, %1;" : "=r"(u) : "f"(f));
    return u;
}
__device__ __forceinline__ float f2tf_val(float f) {
    return __uint_as_float(f2tf(f));
}
#define MMA_TF32(C, A, B)                                                      \
    asm volatile(                                                              \
        "mma.sync.aligned.m16n8k8.row.col.f32.tf32.tf32.f32 "                  \
        "{%0,%1,%2,%3},{%4,%5,%6,%7},{%8,%9},{%0,%1,%2,%3};\n"                 \
        : "+f"((C)[0]), "+f"((C)[1]), "+f"((C)[2]), "+f"((C)[3])               \
        : "r"((A)[0]), "r"((A)[1]), "r"((A)[2]), "r"((A)[3]),                  \
          "r"((B)[0]), "r"((B)[1]))

// ---------------- LayerNorm: warp per token, 8 tokens per block ----------------
template <bool PERM>
__global__ void __launch_bounds__(256)
ln_kernel(const float* __restrict__ x, const float* __restrict__ g,
          const float* __restrict__ b, float* __restrict__ out) {
    int lane = threadIdx.x & 31, wid = threadIdx.x >> 5;
    int n = (blockIdx.x << 3) + wid;
    const float* xp = x + (size_t)n * CDIM;
    float v[6];
#pragma unroll
    for (int i = 0; i < 6; i++) v[i] = xp[lane + (i << 5)];
    float s = 0.f, s2 = 0.f;
#pragma unroll
    for (int i = 0; i < 6; i++) { s += v[i]; s2 += v[i] * v[i]; }
#pragma unroll
    for (int o = 16; o; o >>= 1) {
        s  += __shfl_xor_sync(0xffffffffu, s,  o);
        s2 += __shfl_xor_sync(0xffffffffu, s2, o);
    }
    float mean = s * (1.0f / CDIM);
    float rstd = rsqrtf(s2 * (1.0f / CDIM) - mean * mean + 1e-5f);
    int orow = PERM ? token_to_wrow(n) : n;
    float* op = out + (size_t)orow * CDIM;
#pragma unroll
    for (int i = 0; i < 6; i++) {
        int c = lane + (i << 5);
        op[c] = (v[i] - mean) * rstd * __ldg(g + c) + __ldg(b + c);
    }
}

// ---------------- TF32 tensor-core GEMM 128x128x16, 3-stage, one sync/iter ---------
// MODE 0: C=A*B  1: +bias  2: +bias+resid w/ inverse window permute  3: +bias+resid
template <int MODE>
__global__ void __launch_bounds__(256)
mma_gemm(const float* __restrict__ A, const float* __restrict__ B,
         const float* __restrict__ bias, const float* __restrict__ resid,
         float* __restrict__ C, int N, int K) {
    __shared__ float As[3][128][20];   // [stage][m][k]
    __shared__ float Bs[3][16][136];   // [stage][k][n]
    int tid = threadIdx.x, lane = tid & 31, warp = tid >> 5;
    int wm = warp & 1, wn = warp >> 1;
    int bm = blockIdx.y << 7, bn = blockIdx.x << 7;
    int q = lane & 3, g8 = lane >> 2;

    int ar0 = tid >> 2,         ak0 = (tid & 3) << 2;
    int ar1 = (tid + 256) >> 2, ak1 = ((tid + 256) & 3) << 2;
    int br0 = tid >> 5,         bc0 = (tid & 31) << 2;
    int br1 = (tid + 256) >> 5, bc1 = ((tid + 256) & 31) << 2;

    float c[4][4][4];
#pragma unroll
    for (int mt = 0; mt < 4; mt++)
#pragma unroll
        for (int nt = 0; nt < 4; nt++)
#pragma unroll
            for (int r = 0; r < 4; r++) c[mt][nt][r] = 0.f;

    int KT = K >> 4;   // >= 6 for all our shapes

#define COPY_STAGE(S, K0)                                                        \
    do {                                                                         \
        cp16(&As[S][ar0][ak0], A + (size_t)(bm + ar0) * K + (K0) + ak0);         \
        cp16(&As[S][ar1][ak1], A + (size_t)(bm + ar1) * K + (K0) + ak1);         \
        {                                                                        \
            int gn0 = bn + bc0, gn1 = bn + bc1;                                  \
            const float* bp0 = B + (size_t)((K0) + br0) * N + gn0;               \
            const float* bp1 = B + (size_t)((K0) + br1) * N + gn1;               \
            if (gn0 + 4 <= N) cp16(&Bs[S][br0][bc0], bp0);                       \
            else              cp16z(&Bs[S][br0][bc0], B);                        \
            if (gn1 + 4 <= N) cp16(&Bs[S][br1][bc1], bp1);                       \
            else              cp16z(&Bs[S][br1][bc1], B);                        \
        }                                                                        \
    } while (0)

    COPY_STAGE(0, 0);
    asm volatile("cp.async.commit_group;\n");
    COPY_STAGE(1, 16);
    asm volatile("cp.async.commit_group;\n");

    int s = 0;
    for (int kt = 0; kt < KT; kt++) {
        asm volatile("cp.async.wait_group 1;\n");
        __syncthreads();
        // prefetch stage kt+2 (overwrites stage computed at kt-1; safe: all
        // threads passed this barrier after finishing that compute)
        int sc = s + 2; if (sc >= 3) sc -= 3;
        if (kt + 2 < KT) COPY_STAGE(sc, (kt + 2) << 4);
        asm volatile("cp.async.commit_group;\n");
#pragma unroll
        for (int kk = 0; kk < 16; kk += 8) {
            unsigned af[4][4], bf[4][2];
#pragma unroll
            for (int mt = 0; mt < 4; mt++) {
                int m = wm * 64 + mt * 16 + g8;
                af[mt][0] = __float_as_uint(As[s][m][kk + q]);
                af[mt][1] = __float_as_uint(As[s][m + 8][kk + q]);
                af[mt][2] = __float_as_uint(As[s][m][kk + q + 4]);
                af[mt][3] = __float_as_uint(As[s][m + 8][kk + q + 4]);
            }
#pragma unroll
            for (int nt = 0; nt < 4; nt++) {
                int n = wn * 32 + nt * 8 + g8;
                bf[nt][0] = __float_as_uint(Bs[s][kk + q][n]);
                bf[nt][1] = __float_as_uint(Bs[s][kk + q + 4][n]);
            }
#pragma unroll
            for (int mt = 0; mt < 4; mt++)
#pragma unroll
                for (int nt = 0; nt < 4; nt++)
                    MMA_TF32(c[mt][nt], af[mt], bf[nt]);
        }
        if (++s >= 3) s = 0;
    }
#undef COPY_STAGE

#pragma unroll
    for (int mt = 0; mt < 4; mt++) {
        int row0 = bm + wm * 64 + mt * 16 + g8;
#pragma unroll
        for (int half = 0; half < 2; half++) {
            int row = row0 + half * 8;
            int orow = (MODE == 2) ? wrow_to_token(row) : row;
#pragma unroll
            for (int nt = 0; nt < 4; nt++) {
                int col = bn + wn * 32 + nt * 8 + (q << 1);
                if (col < N) {
                    float v0 = c[mt][nt][half * 2 + 0];
                    float v1 = c[mt][nt][half * 2 + 1];
                    if (MODE >= 1) { v0 += bias[col]; v1 += bias[col + 1]; }
                    if (MODE >= 2) {
                        float2 rr = *(const float2*)(resid + (size_t)orow * N + col);
                        v0 += rr.x; v1 += rr.y;
                    }
                    *(float2*)(C + (size_t)orow * N + col) = make_float2(v0, v1);
                }
            }
        }
    }
}

// ---------------- tensor-core windowed attention: one block per (head, window) ------
#define ATTN_SM_FLOATS (9216 + 8320 + 9216 + 1576 + 256)
__global__ void __launch_bounds__(256)
attn_mma_kernel(const float* __restrict__ qkv, const float* __restrict__ rel_bias,
                float* __restrict__ out) {
    extern __shared__ float sm[];
    float* Ks  = sm;            // [256][36]
    float* Vt  = sm + 9216;     // [32][260]
    float* Ps  = sm + 17536;    // [256][36]  (Q staging, then P)
    float* bsh = sm + 26752;    // [1575]
    int*   sid = (int*)(sm + 28328);

    int head = blockIdx.x, win = blockIdx.y;
    int tid = threadIdx.x, lane = tid & 31, warp = tid >> 5;
    int q = lane & 3, g8 = lane >> 2;
    int m0 = warp << 5;

    const float* base = qkv + (size_t)win * 256 * 576 + head * HD;
    for (int idx = tid; idx < 256 * 32; idx += 256) {
        int r = idx >> 5, d = idx & 31;
        const float* p = base + (size_t)r * 576 + d;
        Ks[r * 36 + d]  = f2tf_val(p[192]);
        Vt[d * 260 + r] = f2tf_val(p[384]);
    }
#pragma unroll 4
    for (int i = 0; i < 32; i++)
        Ps[(m0 + i) * 36 + lane] = base[(size_t)(m0 + i) * 576 + lane];
    for (int i = tid; i < 1575; i += 256) bsh[i] = rel_bias[i * 6 + head];
    {
        int t = tid;
        int gd = ((win >> 6) << 2) | (t >> 6);
        int gh = (((win >> 3) & 7) << 3) | ((t >> 3) & 7);
        int gw = ((win & 7) << 3) | (t & 7);
        sid[t] = ((((gd + 2) & 15) >> 2) << 6) | ((((gh + 4) & 63) >> 3) << 3) |
                 (((gw + 4) & 63) >> 3);
    }
    __syncthreads();

    unsigned qf[2][4][4];
#pragma unroll
    for (int mt = 0; mt < 2; mt++)
#pragma unroll
        for (int kk = 0; kk < 4; kk++) {
            int m = m0 + mt * 16 + g8, k = kk * 8 + q;
            qf[mt][kk][0] = f2tf(Ps[m * 36 + k] * ATTN_SCALE);
            qf[mt][kk][1] = f2tf(Ps[(m + 8) * 36 + k] * ATTN_SCALE);
            qf[mt][kk][2] = f2tf(Ps[m * 36 + k + 4] * ATTN_SCALE);
            qf[mt][kk][3] = f2tf(Ps[(m + 8) * 36 + k + 4] * ATTN_SCALE);
        }
    int rd_[2][2], rh_[2][2], rw_[2][2], msid[2][2];
#pragma unroll
    for (int mt = 0; mt < 2; mt++)
#pragma unroll
        for (int h = 0; h < 2; h++) {
            int r = m0 + mt * 16 + h * 8 + g8;
            rd_[mt][h] = r >> 6; rh_[mt][h] = (r >> 3) & 7; rw_[mt][h] = r & 7;
            msid[mt][h] = sid[r];
        }
    __syncwarp();

    float o[2][4][4];
#pragma unroll
    for (int mt = 0; mt < 2; mt++)
#pragma unroll
        for (int nt = 0; nt < 4; nt++)
#pragma unroll
            for (int e = 0; e < 4; e++) o[mt][nt][e] = 0.f;
    float rs[2][2] = {{0.f, 0.f}, {0.f, 0.f}};

    for (int ck = 0; ck < 256; ck += 32) {
        float s[2][4][4];
#pragma unroll
        for (int mt = 0; mt < 2; mt++)
#pragma unroll
            for (int nt = 0; nt < 4; nt++)
#pragma unroll
                for (int e = 0; e < 4; e++) s[mt][nt][e] = 0.f;
#pragma unroll
        for (int kk = 0; kk < 4; kk++) {
            unsigned kf[4][2];
#pragma unroll
            for (int nt = 0; nt < 4; nt++) {
                int n = ck + nt * 8 + g8;
                kf[nt][0] = __float_as_uint(Ks[n * 36 + kk * 8 + q]);
                kf[nt][1] = __float_as_uint(Ks[n * 36 + kk * 8 + q + 4]);
            }
#pragma unroll
            for (int mt = 0; mt < 2; mt++)
#pragma unroll
                for (int nt = 0; nt < 4; nt++)
                    MMA_TF32(s[mt][nt], qf[mt][kk], kf[nt]);
        }
#pragma unroll
        for (int nt = 0; nt < 4; nt++) {
            int cc = ck + nt * 8;
            int cd = cc >> 6, ch = (cc >> 3) & 7;
            int sc = (q >= 2) ? sid[cc + 4] : sid[cc];
#pragma unroll
            for (int mt = 0; mt < 2; mt++)
#pragma unroll
                for (int h = 0; h < 2; h++) {
                    int bidx = (rd_[mt][h] - cd + 3) * 225 +
                               (rh_[mt][h] - ch + 7) * 15 + rw_[mt][h] + 7 - (q << 1);
                    float p0, p1;
                    if (msid[mt][h] == sc) {
                        p0 = __expf(s[mt][nt][h * 2 + 0] + bsh[bidx]);
                        p1 = __expf(s[mt][nt][h * 2 + 1] + bsh[bidx - 1]);
                    } else { p0 = 0.f; p1 = 0.f; }
                    rs[mt][h] += p0 + p1;
                    int r = m0 + mt * 16 + h * 8 + g8;
                    *(float2*)&Ps[r * 36 + nt * 8 + (q << 1)] =
                        make_float2(f2tf_val(p0), f2tf_val(p1));
                }
        }
        __syncwarp();
#pragma unroll
        for (int kk = 0; kk < 4; kk++) {
            unsigned vf[4][2], pf[2][4];
#pragma unroll
            for (int nto = 0; nto < 4; nto++) {
                int d = nto * 8 + g8;
                vf[nto][0] = __float_as_uint(Vt[d * 260 + ck + kk * 8 + q]);
                vf[nto][1] = __float_as_uint(Vt[d * 260 + ck + kk * 8 + q + 4]);
            }
#pragma unroll
            for (int mt = 0; mt < 2; mt++) {
                int m = m0 + mt * 16 + g8, k = kk * 8 + q;
                pf[mt][0] = __float_as_uint(Ps[m * 36 + k]);
                pf[mt][1] = __float_as_uint(Ps[(m + 8) * 36 + k]);
                pf[mt][2] = __float_as_uint(Ps[m * 36 + k + 4]);
                pf[mt][3] = __float_as_uint(Ps[(m + 8) * 36 + k + 4]);
            }
#pragma unroll
            for (int mt = 0; mt < 2; mt++)
#pragma unroll
                for (int nto = 0; nto < 4; nto++)
                    MMA_TF32(o[mt][nto], pf[mt], vf[nto]);
        }
        __syncwarp();
    }

#pragma unroll
    for (int mt = 0; mt < 2; mt++)
#pragma unroll
        for (int h = 0; h < 2; h++) {
            float v = rs[mt][h];
            v += __shfl_xor_sync(0xffffffffu, v, 1);
            v += __shfl_xor_sync(0xffffffffu, v, 2);
            rs[mt][h] = 1.f / v;
        }
#pragma unroll
    for (int mt = 0; mt < 2; mt++)
#pragma unroll
        for (int h = 0; h < 2; h++) {
            int r = m0 + mt * 16 + h * 8 + g8;
            float* op = out + (size_t)(win * 256 + r) * CDIM + head * HD;
            float inv = rs[mt][h];
#pragma unroll
            for (int nto = 0; nto < 4; nto++)
                *(float2*)(op + nto * 8 + (q << 1)) =
                    make_float2(o[mt][nto][h * 2 + 0] * inv,
                                o[mt][nto][h * 2 + 1] * inv);
        }
}

// ---------------- depthwise 3x3x3 conv + bias + exact GELU ----------------
__global__ void __launch_bounds__(256)
conv_gelu_kernel(const float* __restrict__ hin, const float* __restrict__ wt,
                 const float* __restrict__ cb, float* __restrict__ hout) {
    int n = blockIdx.x;
    int d = n >> 12, h = (n >> 6) & 63, wx = n & 63;
    int tid = threadIdx.x;
#pragma unroll
    for (int jj = 0; jj < 3; jj++) {
        int c = tid + jj * 256;
        float acc = cb[c];
        const float* wc = wt + c * 27;
        int k = 0;
#pragma unroll
        for (int kd = -1; kd <= 1; kd++) {
            int dd = d + kd;
#pragma unroll
            for (int kh = -1; kh <= 1; kh++) {
                int hh = h + kh;
#pragma unroll
                for (int kw = -1; kw <= 1; kw++, k++) {
                    int ww = wx + kw;
                    if ((unsigned)dd < 16u && (unsigned)hh < 64u && (unsigned)ww < 64u) {
                        int nb = (dd << 12) | (hh << 6) | ww;
                        acc += wc[k] * hin[(size_t)nb * HIDDEN + c];
                    }
                }
            }
        }
        float gl = 0.5f * acc * (1.f + erff(acc * 0.70710678118654752f));
        hout[(size_t)n * HIDDEN + c] = gl;
    }
}

// ---------------- launch ----------------
extern "C" void kernel_launch(void* const* d_in, const int* in_sizes, int n_in,
                              void* d_out, int out_size) {
    const float* x     = (const float*)d_in[0];
    const float* n1g   = (const float*)d_in[1];
    const float* n1b   = (const float*)d_in[2];
    const float* qkvw  = (const float*)d_in[3];
    const float* qkvb  = (const float*)d_in[4];
    const float* relb  = (const float*)d_in[5];
    const float* projw = (const float*)d_in[6];
    const float* projb = (const float*)d_in[7];
    const float* n2g   = (const float*)d_in[8];
    const float* n2b   = (const float*)d_in[9];
    const float* fc1A  = (const float*)d_in[10];
    const float* fc1Bw = (const float*)d_in[11];
    const float* fc1Bb = (const float*)d_in[12];
    const float* dww   = (const float*)d_in[13];
    const float* dwb   = (const float*)d_in[14];
    const float* fc2A  = (const float*)d_in[15];
    const float* fc2Bw = (const float*)d_in[16];
    const float* fc2Bb = (const float*)d_in[17];
    float* out = (float*)d_out;

    float *p_tok, *p_qkv, *p_attn, *p_x1, *p_r1, *p_hid, *p_conv, *p_r2;
    cudaGetSymbolAddress((void**)&p_tok,  g_tok192a);
    cudaGetSymbolAddress((void**)&p_qkv,  g_qkv);
    cudaGetSymbolAddress((void**)&p_attn, g_attn);
    cudaGetSymbolAddress((void**)&p_x1,   g_x1);
    cudaGetSymbolAddress((void**)&p_r1,   g_r1);
    cudaGetSymbolAddress((void**)&p_hid,  g_hid);
    cudaGetSymbolAddress((void**)&p_conv, g_conv);
    cudaGetSymbolAddress((void**)&p_r2,   g_r2);

    const int ATTN_SMEM = ATTN_SM_FLOATS * 4;
    cudaFuncSetAttribute(attn_mma_kernel, cudaFuncAttributeMaxDynamicSharedMemorySize, ATTN_SMEM);

    // 1. LN1 + window permute
    ln_kernel<true><<<NTOK / 8, 256>>>(x, n1g, n1b, p_tok);
    // 2. qkv = xw @ qkv_w + b   [65536 x 576], K=192
    mma_gemm<1><<<dim3(5, 512), 256>>>(p_tok, qkvw, qkvb, nullptr, p_qkv, 576, 192);
    // 3. windowed attention (tensor-core)
    attn_mma_kernel<<<dim3(NHEADS, NWIN), 256, ATTN_SMEM>>>(p_qkv, relb, p_attn);
    // 4. proj + inverse permute + residual -> x1 (token order)
    mma_gemm<2><<<dim3(2, 512), 256>>>(p_attn, projw, projb, x, p_x1, 192, 192);
    // 5. LN2
    ln_kernel<false><<<NTOK / 8, 256>>>(p_x1, n2g, n2b, p_tok);
    // 6. r1 = hn @ fc1_A   [65536 x 384], K=192
    mma_gemm<0><<<dim3(3, 512), 256>>>(p_tok, fc1A, nullptr, nullptr, p_r1, 384, 192);
    // 7. hid = r1 @ fc1_Bw + b   [65536 x 768], K=384
    mma_gemm<1><<<dim3(6, 512), 256>>>(p_r1, fc1Bw, fc1Bb, nullptr, p_hid, 768, 384);
    // 8. depthwise conv3d + bias + GELU
    conv_gelu_kernel<<<NTOK, 256>>>(p_hid, dww, dwb, p_conv);
    // 9. r2 = conv @ fc2_A   [65536 x 96], K=768
    mma_gemm<0><<<dim3(1, 512), 256>>>(p_conv, fc2A, nullptr, nullptr, p_r2, 96, 768);
    // 10. out = x1 + r2 @ fc2_Bw + b   [65536 x 192], K=96
    mma_gemm<3><<<dim3(2, 512), 256>>>(p_r2, fc2Bw, fc2Bb, p_x1, out, 192, 96);
}

// round 8
// speedup vs baseline: 1.5973x; 1.0691x over previous
#include <cuda_runtime.h>
#include <cuda_bf16.h>
#include <math.h>

// Problem constants (B=1, D=16, H=64, W=64)
#define NTOK   65536
#define CDIM   192
#define NHEADS 6
#define HD     32
#define HIDDEN 768
#define RANK1  384
#define RANK2  96
#define ATTN_SCALE 0.17677669529663687f  // 32^-0.5

typedef __nv_bfloat16 bf16;

// ---------------- scratch (device globals; no runtime allocation) ----------------
__device__ bf16  g_ln[(size_t)NTOK * CDIM];      // LN1 out (windowed), later LN2 out
__device__ bf16  g_qkv[(size_t)NTOK * 576];
__device__ bf16  g_attn[(size_t)NTOK * CDIM];
__device__ float g_x1[(size_t)NTOK * CDIM];
__device__ bf16  g_r1[(size_t)NTOK * RANK1];
__device__ bf16  g_hid[(size_t)NTOK * HIDDEN];
__device__ bf16  g_conv[(size_t)NTOK * HIDDEN];
__device__ bf16  g_r2[(size_t)NTOK * RANK2];
// transposed bf16 weights [N][K]
__device__ bf16  g_qkvwt[576 * 192];
__device__ bf16  g_projwt[192 * 192];
__device__ bf16  g_fc1At[RANK1 * 192];
__device__ bf16  g_fc1Bt[HIDDEN * RANK1];
__device__ bf16  g_fc2At[RANK2 * HIDDEN];
__device__ bf16  g_fc2Bt[CDIM * RANK2];

// ---------------- helpers ----------------
__device__ __forceinline__ int token_to_wrow(int n) {
    int w = n & 63, h = (n >> 6) & 63, d = n >> 12;
    int win = ((d >> 2) << 6) | ((h >> 3) << 3) | (w >> 3);
    int t   = ((d & 3) << 6) | ((h & 7) << 3) | (w & 7);
    return (win << 8) | t;
}
__device__ __forceinline__ int wrow_to_token(int r) {
    int win = r >> 8, t = r & 255;
    int d = ((win >> 6) << 2) | (t >> 6);
    int h = (((win >> 3) & 7) << 3) | ((t >> 3) & 7);
    int w = ((win & 7) << 3) | (t & 7);
    return (d << 12) | (h << 6) | w;
}
__device__ __forceinline__ void cp16(void* smem, const void* gmem) {
    unsigned s = (unsigned)__cvta_generic_to_shared(smem);
    asm volatile("cp.async.cg.shared.global [%0], [%1], 16;\n" :: "r"(s), "l"(gmem));
}
__device__ __forceinline__ void cp16z(void* smem, const void* gmem) {
    unsigned s = (unsigned)__cvta_generic_to_shared(smem);
    asm volatile("cp.async.cg.shared.global [%0], [%1], 16, 0;\n" :: "r"(s), "l"(gmem));
}
__device__ __forceinline__ unsigned f2tf(float f) {
    unsigned u;
    asm("cvt.rna.tf32.f32 %0, %1;" : "=r"(u) : "f"(f));
    return u;
}
__device__ __forceinline__ float f2tf_val(float f) { return __uint_as_float(f2tf(f)); }

#define MMA_TF32(C, A, B)                                                      \
    asm volatile(                                                              \
        "mma.sync.aligned.m16n8k8.row.col.f32.tf32.tf32.f32 "                  \
        "{%0,%1,%2,%3},{%4,%5,%6,%7},{%8,%9},{%0,%1,%2,%3};\n"                 \
        : "+f"((C)[0]), "+f"((C)[1]), "+f"((C)[2]), "+f"((C)[3])               \
        : "r"((A)[0]), "r"((A)[1]), "r"((A)[2]), "r"((A)[3]),                  \
          "r"((B)[0]), "r"((B)[1]))
#define MMA_BF16(C, A, B)                                                      \
    asm volatile(                                                              \
        "mma.sync.aligned.m16n8k16.row.col.f32.bf16.bf16.f32 "                 \
        "{%0,%1,%2,%3},{%4,%5,%6,%7},{%8,%9},{%0,%1,%2,%3};\n"                 \
        : "+f"((C)[0]), "+f"((C)[1]), "+f"((C)[2]), "+f"((C)[3])               \
        : "r"((A)[0]), "r"((A)[1]), "r"((A)[2]), "r"((A)[3]),                  \
          "r"((B)[0]), "r"((B)[1]))

// ---------------- weight convert + transpose: [K][N] f32 -> [N][K] bf16 -----------
__global__ void wconv_kernel(const float* __restrict__ src, bf16* __restrict__ dst,
                             int K, int N) {
    int idx = blockIdx.x * 256 + threadIdx.x;
    if (idx < K * N) {
        int k = idx / N, n = idx - k * N;
        dst[n * K + k] = __float2bfloat16(src[idx]);
    }
}

// ---------------- LayerNorm: warp per token -> bf16 out ----------------
template <bool PERM>
__global__ void __launch_bounds__(256)
ln_kernel(const float* __restrict__ x, const float* __restrict__ g,
          const float* __restrict__ b, bf16* __restrict__ out) {
    int lane = threadIdx.x & 31, wid = threadIdx.x >> 5;
    int n = (blockIdx.x << 3) + wid;
    const float* xp = x + (size_t)n * CDIM;
    float v[6];
#pragma unroll
    for (int i = 0; i < 6; i++) v[i] = xp[lane + (i << 5)];
    float s = 0.f, s2 = 0.f;
#pragma unroll
    for (int i = 0; i < 6; i++) { s += v[i]; s2 += v[i] * v[i]; }
#pragma unroll
    for (int o = 16; o; o >>= 1) {
        s  += __shfl_xor_sync(0xffffffffu, s,  o);
        s2 += __shfl_xor_sync(0xffffffffu, s2, o);
    }
    float mean = s * (1.0f / CDIM);
    float rstd = rsqrtf(s2 * (1.0f / CDIM) - mean * mean + 1e-5f);
    int orow = PERM ? token_to_wrow(n) : n;
    bf16* op = out + (size_t)orow * CDIM;
#pragma unroll
    for (int i = 0; i < 6; i++) {
        int c = lane + (i << 5);
        op[c] = __float2bfloat16((v[i] - mean) * rstd * __ldg(g + c) + __ldg(b + c));
    }
}

// ---------------- BF16 tensor-core GEMM 128x128x32, 3-stage, one sync/iter ---------
// A: [M][K] bf16 row-major.  B: [N][K] bf16 (pre-transposed weights).
// Tile row stride 40 halves = 80 B (16B-aligned for cp.async, conflict-free frags).
// MODE 0: C=A*B  1: +bias  2: +bias+resid w/ inverse window permute  3: +bias+resid
template <int MODE, bool OUTBF>
__global__ void __launch_bounds__(256)
mma_gemm(const bf16* __restrict__ A, const bf16* __restrict__ B,
         const float* __restrict__ bias, const float* __restrict__ resid,
         void* __restrict__ Cv, int N, int K) {
    __shared__ bf16 As[3][128][40];   // [stage][m][k]
    __shared__ bf16 Bs[3][128][40];   // [stage][n][k]
    int tid = threadIdx.x, lane = tid & 31, warp = tid >> 5;
    int wm = warp & 1, wn = warp >> 1;
    int bm = blockIdx.y << 7, bn = blockIdx.x << 7;
    int q = lane & 3, g8 = lane >> 2;

    float c[4][4][4];
#pragma unroll
    for (int mt = 0; mt < 4; mt++)
#pragma unroll
        for (int nt = 0; nt < 4; nt++)
#pragma unroll
            for (int r = 0; r < 4; r++) c[mt][nt][r] = 0.f;

    int KT = K >> 5;   // k-tile 32; KT>=3 for all shapes

    int r0 = tid >> 2,          o0 = (tid & 3) << 3;         // chunk tid
    int r1 = (tid + 256) >> 2,  o1 = ((tid + 256) & 3) << 3; // chunk tid+256

#define COPY_STAGE(S, K0)                                                        \
    do {                                                                         \
        cp16(&As[S][r0][o0], A + (size_t)(bm + r0) * K + (K0) + o0);             \
        cp16(&As[S][r1][o1], A + (size_t)(bm + r1) * K + (K0) + o1);             \
        if (bn + r0 < N) cp16(&Bs[S][r0][o0], B + (size_t)(bn + r0) * K + (K0) + o0); \
        else             cp16z(&Bs[S][r0][o0], B);                               \
        if (bn + r1 < N) cp16(&Bs[S][r1][o1], B + (size_t)(bn + r1) * K + (K0) + o1); \
        else             cp16z(&Bs[S][r1][o1], B);                               \
    } while (0)

    COPY_STAGE(0, 0);
    asm volatile("cp.async.commit_group;\n");
    COPY_STAGE(1, 32);
    asm volatile("cp.async.commit_group;\n");

    int s = 0;
    for (int kt = 0; kt < KT; kt++) {
        asm volatile("cp.async.wait_group 1;\n");
        __syncthreads();
        int sc = s + 2; if (sc >= 3) sc -= 3;
        if (kt + 2 < KT) COPY_STAGE(sc, (kt + 2) << 5);
        asm volatile("cp.async.commit_group;\n");
#pragma unroll
        for (int kk = 0; kk < 32; kk += 16) {
            unsigned af[4][4], bf[4][2];
#pragma unroll
            for (int mt = 0; mt < 4; mt++) {
                int m = wm * 64 + mt * 16 + g8;
                af[mt][0] = *(const unsigned*)&As[s][m][kk + 2 * q];
                af[mt][1] = *(const unsigned*)&As[s][m + 8][kk + 2 * q];
                af[mt][2] = *(const unsigned*)&As[s][m][kk + 2 * q + 8];
                af[mt][3] = *(const unsigned*)&As[s][m + 8][kk + 2 * q + 8];
            }
#pragma unroll
            for (int nt = 0; nt < 4; nt++) {
                int n = wn * 32 + nt * 8 + g8;
                bf[nt][0] = *(const unsigned*)&Bs[s][n][kk + 2 * q];
                bf[nt][1] = *(const unsigned*)&Bs[s][n][kk + 2 * q + 8];
            }
#pragma unroll
            for (int mt = 0; mt < 4; mt++)
#pragma unroll
                for (int nt = 0; nt < 4; nt++)
                    MMA_BF16(c[mt][nt], af[mt], bf[nt]);
        }
        if (++s >= 3) s = 0;
    }
#undef COPY_STAGE

#pragma unroll
    for (int mt = 0; mt < 4; mt++) {
        int row0 = bm + wm * 64 + mt * 16 + g8;
#pragma unroll
        for (int half = 0; half < 2; half++) {
            int row = row0 + half * 8;
            int orow = (MODE == 2) ? wrow_to_token(row) : row;
#pragma unroll
            for (int nt = 0; nt < 4; nt++) {
                int col = bn + wn * 32 + nt * 8 + (q << 1);
                if (col < N) {
                    float v0 = c[mt][nt][half * 2 + 0];
                    float v1 = c[mt][nt][half * 2 + 1];
                    if (MODE >= 1) { v0 += bias[col]; v1 += bias[col + 1]; }
                    if (MODE >= 2) {
                        float2 rr = *(const float2*)(resid + (size_t)orow * N + col);
                        v0 += rr.x; v1 += rr.y;
                    }
                    if (OUTBF) {
                        *( __nv_bfloat162*)((bf16*)Cv + (size_t)orow * N + col) =
                            __floats2bfloat162_rn(v0, v1);
                    } else {
                        *(float2*)((float*)Cv + (size_t)orow * N + col) =
                            make_float2(v0, v1);
                    }
                }
            }
        }
    }
}

// ---------------- tensor-core windowed attention (tf32 internals, bf16 I/O) --------
#define ATTN_SM_FLOATS (9216 + 8320 + 9216 + 1576 + 256)
__global__ void __launch_bounds__(256)
attn_mma_kernel(const bf16* __restrict__ qkv, const float* __restrict__ rel_bias,
                bf16* __restrict__ out) {
    extern __shared__ float sm[];
    float* Ks  = sm;            // [256][36]
    float* Vt  = sm + 9216;     // [32][260]
    float* Ps  = sm + 17536;    // [256][36]  (Q staging, then P)
    float* bsh = sm + 26752;    // [1575]
    int*   sid = (int*)(sm + 28328);

    int head = blockIdx.x, win = blockIdx.y;
    int tid = threadIdx.x, lane = tid & 31, warp = tid >> 5;
    int q = lane & 3, g8 = lane >> 2;
    int m0 = warp << 5;

    const bf16* base = qkv + (size_t)win * 256 * 576 + head * HD;
    for (int idx = tid; idx < 256 * 32; idx += 256) {
        int r = idx >> 5, d = idx & 31;
        const bf16* p = base + (size_t)r * 576 + d;
        Ks[r * 36 + d]  = __bfloat162float(p[192]);   // bf16 exact in tf32
        Vt[d * 260 + r] = __bfloat162float(p[384]);
    }
#pragma unroll 4
    for (int i = 0; i < 32; i++)
        Ps[(m0 + i) * 36 + lane] = __bfloat162float(base[(size_t)(m0 + i) * 576 + lane]);
    for (int i = tid; i < 1575; i += 256) bsh[i] = rel_bias[i * 6 + head];
    {
        int t = tid;
        int gd = ((win >> 6) << 2) | (t >> 6);
        int gh = (((win >> 3) & 7) << 3) | ((t >> 3) & 7);
        int gw = ((win & 7) << 3) | (t & 7);
        sid[t] = ((((gd + 2) & 15) >> 2) << 6) | ((((gh + 4) & 63) >> 3) << 3) |
                 (((gw + 4) & 63) >> 3);
    }
    __syncthreads();

    unsigned qf[2][4][4];
#pragma unroll
    for (int mt = 0; mt < 2; mt++)
#pragma unroll
        for (int kk = 0; kk < 4; kk++) {
            int m = m0 + mt * 16 + g8, k = kk * 8 + q;
            qf[mt][kk][0] = f2tf(Ps[m * 36 + k] * ATTN_SCALE);
            qf[mt][kk][1] = f2tf(Ps[(m + 8) * 36 + k] * ATTN_SCALE);
            qf[mt][kk][2] = f2tf(Ps[m * 36 + k + 4] * ATTN_SCALE);
            qf[mt][kk][3] = f2tf(Ps[(m + 8) * 36 + k + 4] * ATTN_SCALE);
        }
    int rd_[2][2], rh_[2][2], rw_[2][2], msid[2][2];
#pragma unroll
    for (int mt = 0; mt < 2; mt++)
#pragma unroll
        for (int h = 0; h < 2; h++) {
            int r = m0 + mt * 16 + h * 8 + g8;
            rd_[mt][h] = r >> 6; rh_[mt][h] = (r >> 3) & 7; rw_[mt][h] = r & 7;
            msid[mt][h] = sid[r];
        }
    __syncwarp();

    float o[2][4][4];
#pragma unroll
    for (int mt = 0; mt < 2; mt++)
#pragma unroll
        for (int nt = 0; nt < 4; nt++)
#pragma unroll
            for (int e = 0; e < 4; e++) o[mt][nt][e] = 0.f;
    float rs[2][2] = {{0.f, 0.f}, {0.f, 0.f}};

    for (int ck = 0; ck < 256; ck += 32) {
        float s[2][4][4];
#pragma unroll
        for (int mt = 0; mt < 2; mt++)
#pragma unroll
            for (int nt = 0; nt < 4; nt++)
#pragma unroll
                for (int e = 0; e < 4; e++) s[mt][nt][e] = 0.f;
#pragma unroll
        for (int kk = 0; kk < 4; kk++) {
            unsigned kf[4][2];
#pragma unroll
            for (int nt = 0; nt < 4; nt++) {
                int n = ck + nt * 8 + g8;
                kf[nt][0] = __float_as_uint(Ks[n * 36 + kk * 8 + q]);
                kf[nt][1] = __float_as_uint(Ks[n * 36 + kk * 8 + q + 4]);
            }
#pragma unroll
            for (int mt = 0; mt < 2; mt++)
#pragma unroll
                for (int nt = 0; nt < 4; nt++)
                    MMA_TF32(s[mt][nt], qf[mt][kk], kf[nt]);
        }
#pragma unroll
        for (int nt = 0; nt < 4; nt++) {
            int cc = ck + nt * 8;
            int cd = cc >> 6, ch = (cc >> 3) & 7;
            int sc = (q >= 2) ? sid[cc + 4] : sid[cc];
#pragma unroll
            for (int mt = 0; mt < 2; mt++)
#pragma unroll
                for (int h = 0; h < 2; h++) {
                    int bidx = (rd_[mt][h] - cd + 3) * 225 +
                               (rh_[mt][h] - ch + 7) * 15 + rw_[mt][h] + 7 - (q << 1);
                    float p0, p1;
                    if (msid[mt][h] == sc) {
                        p0 = __expf(s[mt][nt][h * 2 + 0] + bsh[bidx]);
                        p1 = __expf(s[mt][nt][h * 2 + 1] + bsh[bidx - 1]);
                    } else { p0 = 0.f; p1 = 0.f; }
                    rs[mt][h] += p0 + p1;
                    int r = m0 + mt * 16 + h * 8 + g8;
                    *(float2*)&Ps[r * 36 + nt * 8 + (q << 1)] =
                        make_float2(f2tf_val(p0), f2tf_val(p1));
                }
        }
        __syncwarp();
#pragma unroll
        for (int kk = 0; kk < 4; kk++) {
            unsigned vf[4][2], pf[2][4];
#pragma unroll
            for (int nto = 0; nto < 4; nto++) {
                int d = nto * 8 + g8;
                vf[nto][0] = __float_as_uint(Vt[d * 260 + ck + kk * 8 + q]);
                vf[nto][1] = __float_as_uint(Vt[d * 260 + ck + kk * 8 + q + 4]);
            }
#pragma unroll
            for (int mt = 0; mt < 2; mt++) {
                int m = m0 + mt * 16 + g8, k = kk * 8 + q;
                pf[mt][0] = __float_as_uint(Ps[m * 36 + k]);
                pf[mt][1] = __float_as_uint(Ps[(m + 8) * 36 + k]);
                pf[mt][2] = __float_as_uint(Ps[m * 36 + k + 4]);
                pf[mt][3] = __float_as_uint(Ps[(m + 8) * 36 + k + 4]);
            }
#pragma unroll
            for (int mt = 0; mt < 2; mt++)
#pragma unroll
                for (int nto = 0; nto < 4; nto++)
                    MMA_TF32(o[mt][nto], pf[mt], vf[nto]);
        }
        __syncwarp();
    }

#pragma unroll
    for (int mt = 0; mt < 2; mt++)
#pragma unroll
        for (int h = 0; h < 2; h++) {
            float v = rs[mt][h];
            v += __shfl_xor_sync(0xffffffffu, v, 1);
            v += __shfl_xor_sync(0xffffffffu, v, 2);
            rs[mt][h] = 1.f / v;
        }
#pragma unroll
    for (int mt = 0; mt < 2; mt++)
#pragma unroll
        for (int h = 0; h < 2; h++) {
            int r = m0 + mt * 16 + h * 8 + g8;
            bf16* op = out + (size_t)(win * 256 + r) * CDIM + head * HD;
            float inv = rs[mt][h];
#pragma unroll
            for (int nto = 0; nto < 4; nto++)
                *(__nv_bfloat162*)(op + nto * 8 + (q << 1)) =
                    __floats2bfloat162_rn(o[mt][nto][h * 2 + 0] * inv,
                                          o[mt][nto][h * 2 + 1] * inv);
        }
}

// ---------------- depthwise 3x3x3 conv + bias + exact GELU (bf16 I/O) --------------
__global__ void __launch_bounds__(256)
conv_gelu_kernel(const bf16* __restrict__ hin, const float* __restrict__ wt,
                 const float* __restrict__ cb, bf16* __restrict__ hout) {
    int n = blockIdx.x;
    int d = n >> 12, h = (n >> 6) & 63, wx = n & 63;
    int tid = threadIdx.x;
#pragma unroll
    for (int jj = 0; jj < 3; jj++) {
        int c = tid + jj * 256;
        float acc = cb[c];
        const float* wc = wt + c * 27;
        int k = 0;
#pragma unroll
        for (int kd = -1; kd <= 1; kd++) {
            int dd = d + kd;
#pragma unroll
            for (int kh = -1; kh <= 1; kh++) {
                int hh = h + kh;
#pragma unroll
                for (int kw = -1; kw <= 1; kw++, k++) {
                    int ww = wx + kw;
                    if ((unsigned)dd < 16u && (unsigned)hh < 64u && (unsigned)ww < 64u) {
                        int nb = (dd << 12) | (hh << 6) | ww;
                        acc += wc[k] * __bfloat162float(hin[(size_t)nb * HIDDEN + c]);
                    }
                }
            }
        }
        float gl = 0.5f * acc * (1.f + erff(acc * 0.70710678118654752f));
        hout[(size_t)n * HIDDEN + c] = __float2bfloat16(gl);
    }
}

// ---------------- launch ----------------
extern "C" void kernel_launch(void* const* d_in, const int* in_sizes, int n_in,
                              void* d_out, int out_size) {
    const float* x     = (const float*)d_in[0];
    const float* n1g   = (const float*)d_in[1];
    const float* n1b   = (const float*)d_in[2];
    const float* qkvw  = (const float*)d_in[3];
    const float* qkvb  = (const float*)d_in[4];
    const float* relb  = (const float*)d_in[5];
    const float* projw = (const float*)d_in[6];
    const float* projb = (const float*)d_in[7];
    const float* n2g   = (const float*)d_in[8];
    const float* n2b   = (const float*)d_in[9];
    const float* fc1A  = (const float*)d_in[10];
    const float* fc1Bw = (const float*)d_in[11];
    const float* fc1Bb = (const float*)d_in[12];
    const float* dww   = (const float*)d_in[13];
    const float* dwb   = (const float*)d_in[14];
    const float* fc2A  = (const float*)d_in[15];
    const float* fc2Bw = (const float*)d_in[16];
    const float* fc2Bb = (const float*)d_in[17];
    float* out = (float*)d_out;

    bf16 *p_ln, *p_qkv, *p_attn, *p_r1, *p_hid, *p_conv, *p_r2;
    bf16 *p_qkvwt, *p_projwt, *p_fc1At, *p_fc1Bt, *p_fc2At, *p_fc2Bt;
    float *p_x1;
    cudaGetSymbolAddress((void**)&p_ln,    g_ln);
    cudaGetSymbolAddress((void**)&p_qkv,   g_qkv);
    cudaGetSymbolAddress((void**)&p_attn,  g_attn);
    cudaGetSymbolAddress((void**)&p_x1,    g_x1);
    cudaGetSymbolAddress((void**)&p_r1,    g_r1);
    cudaGetSymbolAddress((void**)&p_hid,   g_hid);
    cudaGetSymbolAddress((void**)&p_conv,  g_conv);
    cudaGetSymbolAddress((void**)&p_r2,    g_r2);
    cudaGetSymbolAddress((void**)&p_qkvwt, g_qkvwt);
    cudaGetSymbolAddress((void**)&p_projwt, g_projwt);
    cudaGetSymbolAddress((void**)&p_fc1At, g_fc1At);
    cudaGetSymbolAddress((void**)&p_fc1Bt, g_fc1Bt);
    cudaGetSymbolAddress((void**)&p_fc2At, g_fc2At);
    cudaGetSymbolAddress((void**)&p_fc2Bt, g_fc2Bt);

    const int ATTN_SMEM = ATTN_SM_FLOATS * 4;
    cudaFuncSetAttribute(attn_mma_kernel, cudaFuncAttributeMaxDynamicSharedMemorySize, ATTN_SMEM);

    // 0. weight convert+transpose (bf16, [N][K])
    wconv_kernel<<<(192 * 576 + 255) / 256, 256>>>(qkvw,  p_qkvwt, 192, 576);
    wconv_kernel<<<(192 * 192 + 255) / 256, 256>>>(projw, p_projwt, 192, 192);
    wconv_kernel<<<(192 * 384 + 255) / 256, 256>>>(fc1A,  p_fc1At, 192, 384);
    wconv_kernel<<<(384 * 768 + 255) / 256, 256>>>(fc1Bw, p_fc1Bt, 384, 768);
    wconv_kernel<<<(768 * 96 + 255) / 256, 256>>>(fc2A,  p_fc2At, 768, 96);
    wconv_kernel<<<(96 * 192 + 255) / 256, 256>>>(fc2Bw, p_fc2Bt, 96, 192);

    // 1. LN1 + window permute (bf16 out)
    ln_kernel<true><<<NTOK / 8, 256>>>(x, n1g, n1b, p_ln);
    // 2. qkv = xw @ qkv_w + b   [65536 x 576], K=192  (bf16 out)
    mma_gemm<1, true><<<dim3(5, 512), 256>>>(p_ln, p_qkvwt, qkvb, nullptr, p_qkv, 576, 192);
    // 3. windowed attention (bf16 out)
    attn_mma_kernel<<<dim3(NHEADS, 256), 256, ATTN_SMEM>>>(p_qkv, relb, p_attn);
    // 4. proj + inverse permute + residual -> x1 fp32
    mma_gemm<2, false><<<dim3(2, 512), 256>>>(p_attn, p_projwt, projb, x, p_x1, 192, 192);
    // 5. LN2 (bf16 out)
    ln_kernel<false><<<NTOK / 8, 256>>>(p_x1, n2g, n2b, p_ln);
    // 6. r1 = hn @ fc1_A   [65536 x 384], K=192 (bf16)
    mma_gemm<0, true><<<dim3(3, 512), 256>>>(p_ln, p_fc1At, nullptr, nullptr, p_r1, 384, 192);
    // 7. hid = r1 @ fc1_Bw + b   [65536 x 768], K=384 (bf16)
    mma_gemm<1, true><<<dim3(6, 512), 256>>>(p_r1, p_fc1Bt, fc1Bb, nullptr, p_hid, 768, 384);
    // 8. depthwise conv3d + bias + GELU (bf16)
    conv_gelu_kernel<<<NTOK, 256>>>(p_hid, dww, dwb, p_conv);
    // 9. r2 = conv @ fc2_A   [65536 x 96], K=768 (bf16)
    mma_gemm<0, true><<<dim3(1, 512), 256>>>(p_conv, p_fc2At, nullptr, nullptr, p_r2, 96, 768);
    // 10. out = x1 + r2 @ fc2_Bw + b   [65536 x 192], K=96 (fp32)
    mma_gemm<3, false><<<dim3(2, 512), 256>>>(p_r2, p_fc2Bt, fc2Bb, p_x1, out, 192, 96);
}

// round 9
// speedup vs baseline: 3.1003x; 1.9410x over previous
#include <cuda_runtime.h>
#include <cuda_bf16.h>
#include <math.h>

// Problem constants (B=1, D=16, H=64, W=64)
#define NTOK   65536
#define CDIM   192
#define NHEADS 6
#define HD     32
#define HIDDEN 768
#define RANK1  384
#define RANK2  96
#define ATTN_SCALE 0.17677669529663687f  // 32^-0.5

typedef __nv_bfloat16 bf16;

// ---------------- scratch (device globals; no runtime allocation) ----------------
__device__ bf16  g_ln[(size_t)NTOK * CDIM];
__device__ bf16  g_qkv[(size_t)NTOK * 576];
__device__ bf16  g_attn[(size_t)NTOK * CDIM];
__device__ float g_x1[(size_t)NTOK * CDIM];
__device__ bf16  g_r1[(size_t)NTOK * RANK1];
__device__ bf16  g_hid[(size_t)NTOK * HIDDEN];
__device__ bf16  g_conv[(size_t)NTOK * HIDDEN];
__device__ bf16  g_r2[(size_t)NTOK * RANK2];
// transposed bf16 weights [N][K]
__device__ bf16  g_qkvwt[576 * 192];
__device__ bf16  g_projwt[192 * 192];
__device__ bf16  g_fc1At[RANK1 * 192];
__device__ bf16  g_fc1Bt[HIDDEN * RANK1];
__device__ bf16  g_fc2At[RANK2 * HIDDEN];
__device__ bf16  g_fc2Bt[CDIM * RANK2];

// ---------------- helpers ----------------
__device__ __forceinline__ int token_to_wrow(int n) {
    int w = n & 63, h = (n >> 6) & 63, d = n >> 12;
    int win = ((d >> 2) << 6) | ((h >> 3) << 3) | (w >> 3);
    int t   = ((d & 3) << 6) | ((h & 7) << 3) | (w & 7);
    return (win << 8) | t;
}
__device__ __forceinline__ int wrow_to_token(int r) {
    int win = r >> 8, t = r & 255;
    int d = ((win >> 6) << 2) | (t >> 6);
    int h = (((win >> 3) & 7) << 3) | ((t >> 3) & 7);
    int w = ((win & 7) << 3) | (t & 7);
    return (d << 12) | (h << 6) | w;
}
__device__ __forceinline__ void cp16(void* smem, const void* gmem) {
    unsigned s = (unsigned)__cvta_generic_to_shared(smem);
    asm volatile("cp.async.cg.shared.global [%0], [%1], 16;\n" :: "r"(s), "l"(gmem));
}
__device__ __forceinline__ void cp16z(void* smem, const void* gmem) {
    unsigned s = (unsigned)__cvta_generic_to_shared(smem);
    asm volatile("cp.async.cg.shared.global [%0], [%1], 16, 0;\n" :: "r"(s), "l"(gmem));
}
#define MMA_BF16(C, A, B)                                                      \
    asm volatile(                                                              \
        "mma.sync.aligned.m16n8k16.row.col.f32.bf16.bf16.f32 "                 \
        "{%0,%1,%2,%3},{%4,%5,%6,%7},{%8,%9},{%0,%1,%2,%3};\n"                 \
        : "+f"((C)[0]), "+f"((C)[1]), "+f"((C)[2]), "+f"((C)[3])               \
        : "r"((A)[0]), "r"((A)[1]), "r"((A)[2]), "r"((A)[3]),                  \
          "r"((B)[0]), "r"((B)[1]))

// ---------------- weight convert + transpose: [K][N] f32 -> [N][K] bf16 -----------
__global__ void wconv_kernel(const float* __restrict__ src, bf16* __restrict__ dst,
                             int K, int N) {
    int idx = blockIdx.x * 256 + threadIdx.x;
    if (idx < K * N) {
        int k = idx / N, n = idx - k * N;
        dst[n * K + k] = __float2bfloat16(src[idx]);
    }
}

// ---------------- LayerNorm: warp per token -> bf16 out ----------------
template <bool PERM>
__global__ void __launch_bounds__(256)
ln_kernel(const float* __restrict__ x, const float* __restrict__ g,
          const float* __restrict__ b, bf16* __restrict__ out) {
    int lane = threadIdx.x & 31, wid = threadIdx.x >> 5;
    int n = (blockIdx.x << 3) + wid;
    const float* xp = x + (size_t)n * CDIM;
    float v[6];
#pragma unroll
    for (int i = 0; i < 6; i++) v[i] = xp[lane + (i << 5)];
    float s = 0.f, s2 = 0.f;
#pragma unroll
    for (int i = 0; i < 6; i++) { s += v[i]; s2 += v[i] * v[i]; }
#pragma unroll
    for (int o = 16; o; o >>= 1) {
        s  += __shfl_xor_sync(0xffffffffu, s,  o);
        s2 += __shfl_xor_sync(0xffffffffu, s2, o);
    }
    float mean = s * (1.0f / CDIM);
    float rstd = rsqrtf(s2 * (1.0f / CDIM) - mean * mean + 1e-5f);
    int orow = PERM ? token_to_wrow(n) : n;
    bf16* op = out + (size_t)orow * CDIM;
#pragma unroll
    for (int i = 0; i < 6; i++) {
        int c = lane + (i << 5);
        op[c] = __float2bfloat16((v[i] - mean) * rstd * __ldg(g + c) + __ldg(b + c));
    }
}

// ---------------- BF16 tensor-core GEMM 128x128x32, 3-stage, one sync/iter ---------
template <int MODE, bool OUTBF>
__global__ void __launch_bounds__(256)
mma_gemm(const bf16* __restrict__ A, const bf16* __restrict__ B,
         const float* __restrict__ bias, const float* __restrict__ resid,
         void* __restrict__ Cv, int N, int K) {
    __shared__ bf16 As[3][128][40];
    __shared__ bf16 Bs[3][128][40];
    int tid = threadIdx.x, lane = tid & 31, warp = tid >> 5;
    int wm = warp & 1, wn = warp >> 1;
    int bm = blockIdx.y << 7, bn = blockIdx.x << 7;
    int q = lane & 3, g8 = lane >> 2;

    float c[4][4][4];
#pragma unroll
    for (int mt = 0; mt < 4; mt++)
#pragma unroll
        for (int nt = 0; nt < 4; nt++)
#pragma unroll
            for (int r = 0; r < 4; r++) c[mt][nt][r] = 0.f;

    int KT = K >> 5;

    int r0 = tid >> 2,          o0 = (tid & 3) << 3;
    int r1 = (tid + 256) >> 2,  o1 = ((tid + 256) & 3) << 3;

#define COPY_STAGE(S, K0)                                                        \
    do {                                                                         \
        cp16(&As[S][r0][o0], A + (size_t)(bm + r0) * K + (K0) + o0);             \
        cp16(&As[S][r1][o1], A + (size_t)(bm + r1) * K + (K0) + o1);             \
        if (bn + r0 < N) cp16(&Bs[S][r0][o0], B + (size_t)(bn + r0) * K + (K0) + o0); \
        else             cp16z(&Bs[S][r0][o0], B);                               \
        if (bn + r1 < N) cp16(&Bs[S][r1][o1], B + (size_t)(bn + r1) * K + (K0) + o1); \
        else             cp16z(&Bs[S][r1][o1], B);                               \
    } while (0)

    COPY_STAGE(0, 0);
    asm volatile("cp.async.commit_group;\n");
    COPY_STAGE(1, 32);
    asm volatile("cp.async.commit_group;\n");

    int s = 0;
    for (int kt = 0; kt < KT; kt++) {
        asm volatile("cp.async.wait_group 1;\n");
        __syncthreads();
        int sc = s + 2; if (sc >= 3) sc -= 3;
        if (kt + 2 < KT) COPY_STAGE(sc, (kt + 2) << 5);
        asm volatile("cp.async.commit_group;\n");
#pragma unroll
        for (int kk = 0; kk < 32; kk += 16) {
            unsigned af[4][4], bf[4][2];
#pragma unroll
            for (int mt = 0; mt < 4; mt++) {
                int m = wm * 64 + mt * 16 + g8;
                af[mt][0] = *(const unsigned*)&As[s][m][kk + 2 * q];
                af[mt][1] = *(const unsigned*)&As[s][m + 8][kk + 2 * q];
                af[mt][2] = *(const unsigned*)&As[s][m][kk + 2 * q + 8];
                af[mt][3] = *(const unsigned*)&As[s][m + 8][kk + 2 * q + 8];
            }
#pragma unroll
            for (int nt = 0; nt < 4; nt++) {
                int n = wn * 32 + nt * 8 + g8;
                bf[nt][0] = *(const unsigned*)&Bs[s][n][kk + 2 * q];
                bf[nt][1] = *(const unsigned*)&Bs[s][n][kk + 2 * q + 8];
            }
#pragma unroll
            for (int mt = 0; mt < 4; mt++)
#pragma unroll
                for (int nt = 0; nt < 4; nt++)
                    MMA_BF16(c[mt][nt], af[mt], bf[nt]);
        }
        if (++s >= 3) s = 0;
    }
#undef COPY_STAGE

#pragma unroll
    for (int mt = 0; mt < 4; mt++) {
        int row0 = bm + wm * 64 + mt * 16 + g8;
#pragma unroll
        for (int half = 0; half < 2; half++) {
            int row = row0 + half * 8;
            int orow = (MODE == 2) ? wrow_to_token(row) : row;
#pragma unroll
            for (int nt = 0; nt < 4; nt++) {
                int col = bn + wn * 32 + nt * 8 + (q << 1);
                if (col < N) {
                    float v0 = c[mt][nt][half * 2 + 0];
                    float v1 = c[mt][nt][half * 2 + 1];
                    if (MODE >= 1) { v0 += bias[col]; v1 += bias[col + 1]; }
                    if (MODE >= 2) {
                        float2 rr = *(const float2*)(resid + (size_t)orow * N + col);
                        v0 += rr.x; v1 += rr.y;
                    }
                    if (OUTBF) {
                        *( __nv_bfloat162*)((bf16*)Cv + (size_t)orow * N + col) =
                            __floats2bfloat162_rn(v0, v1);
                    } else {
                        *(float2*)((float*)Cv + (size_t)orow * N + col) =
                            make_float2(v0, v1);
                    }
                }
            }
        }
    }
}

// ---------------- bf16 tensor-core windowed attention ------------------------------
// smem bytes: Ks 20480 | Vt 16896 | Ps 20480 | bsh 6300 | sid 1024  = 65180
#define ATTN_SMEM_BYTES 65184
__global__ void __launch_bounds__(256)
attn_mma_kernel(const bf16* __restrict__ qkv, const float* __restrict__ rel_bias,
                bf16* __restrict__ out) {
    extern __shared__ char smc[];
    bf16*  Ks  = (bf16*)smc;             // [256][40]
    bf16*  Vt  = (bf16*)(smc + 20480);   // [32][264]
    bf16*  Ps  = (bf16*)(smc + 37376);   // [256][40]  (Q staging, then P)
    float* bsh = (float*)(smc + 57856);  // [1575]
    int*   sid = (int*)(smc + 64160);    // [256]

    int head = blockIdx.x, win = blockIdx.y;
    int tid = threadIdx.x, lane = tid & 31, warp = tid >> 5;
    int q = lane & 3, g8 = lane >> 2;
    int m0 = warp << 5;

    const bf16* base = qkv + (size_t)win * 256 * 576 + head * HD;
    for (int idx = tid; idx < 256 * 32; idx += 256) {
        int r = idx >> 5, d = idx & 31;
        const bf16* p = base + (size_t)r * 576 + d;
        Ks[r * 40 + d]  = p[192];
        Vt[d * 264 + r] = p[384];
    }
#pragma unroll 4
    for (int i = 0; i < 32; i++)
        Ps[(m0 + i) * 40 + lane] = base[(size_t)(m0 + i) * 576 + lane];
    for (int i = tid; i < 1575; i += 256) bsh[i] = rel_bias[i * 6 + head];
    {
        int t = tid;
        int gd = ((win >> 6) << 2) | (t >> 6);
        int gh = (((win >> 3) & 7) << 3) | ((t >> 3) & 7);
        int gw = ((win & 7) << 3) | (t & 7);
        sid[t] = ((((gd + 2) & 15) >> 2) << 6) | ((((gh + 4) & 63) >> 3) << 3) |
                 (((gw + 4) & 63) >> 3);
    }
    __syncthreads();

    // Q fragments (raw bf16; scale applied post-MMA)
    unsigned qf[2][2][4];
#pragma unroll
    for (int mt = 0; mt < 2; mt++)
#pragma unroll
        for (int ks = 0; ks < 2; ks++) {
            int m = m0 + mt * 16 + g8, k = ks * 16 + 2 * q;
            qf[mt][ks][0] = *(const unsigned*)&Ps[m * 40 + k];
            qf[mt][ks][1] = *(const unsigned*)&Ps[(m + 8) * 40 + k];
            qf[mt][ks][2] = *(const unsigned*)&Ps[m * 40 + k + 8];
            qf[mt][ks][3] = *(const unsigned*)&Ps[(m + 8) * 40 + k + 8];
        }
    int rd_[2][2], rh_[2][2], rw_[2][2], msid[2][2];
#pragma unroll
    for (int mt = 0; mt < 2; mt++)
#pragma unroll
        for (int h = 0; h < 2; h++) {
            int r = m0 + mt * 16 + h * 8 + g8;
            rd_[mt][h] = r >> 6; rh_[mt][h] = (r >> 3) & 7; rw_[mt][h] = r & 7;
            msid[mt][h] = sid[r];
        }
    __syncwarp();

    float o[2][4][4];
#pragma unroll
    for (int mt = 0; mt < 2; mt++)
#pragma unroll
        for (int nt = 0; nt < 4; nt++)
#pragma unroll
            for (int e = 0; e < 4; e++) o[mt][nt][e] = 0.f;
    float rs[2][2] = {{0.f, 0.f}, {0.f, 0.f}};

    for (int ck = 0; ck < 256; ck += 32) {
        // ---- S = Q K^T ----
        float s[2][4][4];
#pragma unroll
        for (int mt = 0; mt < 2; mt++)
#pragma unroll
            for (int nt = 0; nt < 4; nt++)
#pragma unroll
                for (int e = 0; e < 4; e++) s[mt][nt][e] = 0.f;
#pragma unroll
        for (int ks = 0; ks < 2; ks++) {
            unsigned kf[4][2];
#pragma unroll
            for (int nt = 0; nt < 4; nt++) {
                int n = ck + nt * 8 + g8;
                kf[nt][0] = *(const unsigned*)&Ks[n * 40 + ks * 16 + 2 * q];
                kf[nt][1] = *(const unsigned*)&Ks[n * 40 + ks * 16 + 2 * q + 8];
            }
#pragma unroll
            for (int mt = 0; mt < 2; mt++)
#pragma unroll
                for (int nt = 0; nt < 4; nt++)
                    MMA_BF16(s[mt][nt], qf[mt][ks], kf[nt]);
        }
        // ---- scale + bias + mask + exp, rowsum, P -> smem (bf16) ----
#pragma unroll
        for (int nt = 0; nt < 4; nt++) {
            int cc = ck + nt * 8;
            int cd = cc >> 6, ch = (cc >> 3) & 7;
            int sc = (q >= 2) ? sid[cc + 4] : sid[cc];
#pragma unroll
            for (int mt = 0; mt < 2; mt++)
#pragma unroll
                for (int h = 0; h < 2; h++) {
                    int bidx = (rd_[mt][h] - cd + 3) * 225 +
                               (rh_[mt][h] - ch + 7) * 15 + rw_[mt][h] + 7 - (q << 1);
                    float p0, p1;
                    if (msid[mt][h] == sc) {
                        p0 = __expf(fmaf(s[mt][nt][h * 2 + 0], ATTN_SCALE, bsh[bidx]));
                        p1 = __expf(fmaf(s[mt][nt][h * 2 + 1], ATTN_SCALE, bsh[bidx - 1]));
                    } else { p0 = 0.f; p1 = 0.f; }
                    __nv_bfloat162 pp = __floats2bfloat162_rn(p0, p1);
                    rs[mt][h] += __bfloat162float(pp.x) + __bfloat162float(pp.y);
                    int r = m0 + mt * 16 + h * 8 + g8;
                    *(__nv_bfloat162*)&Ps[r * 40 + nt * 8 + (q << 1)] = pp;
                }
        }
        __syncwarp();
        // ---- O += P V ----
#pragma unroll
        for (int ks = 0; ks < 2; ks++) {
            unsigned vf[4][2], pf[2][4];
#pragma unroll
            for (int nto = 0; nto < 4; nto++) {
                int d = nto * 8 + g8;
                vf[nto][0] = *(const unsigned*)&Vt[d * 264 + ck + ks * 16 + 2 * q];
                vf[nto][1] = *(const unsigned*)&Vt[d * 264 + ck + ks * 16 + 2 * q + 8];
            }
#pragma unroll
            for (int mt = 0; mt < 2; mt++) {
                int m = m0 + mt * 16 + g8, k = ks * 16 + 2 * q;
                pf[mt][0] = *(const unsigned*)&Ps[m * 40 + k];
                pf[mt][1] = *(const unsigned*)&Ps[(m + 8) * 40 + k];
                pf[mt][2] = *(const unsigned*)&Ps[m * 40 + k + 8];
                pf[mt][3] = *(const unsigned*)&Ps[(m + 8) * 40 + k + 8];
            }
#pragma unroll
            for (int mt = 0; mt < 2; mt++)
#pragma unroll
                for (int nto = 0; nto < 4; nto++)
                    MMA_BF16(o[mt][nto], pf[mt], vf[nto]);
        }
        __syncwarp();
    }

#pragma unroll
    for (int mt = 0; mt < 2; mt++)
#pragma unroll
        for (int h = 0; h < 2; h++) {
            float v = rs[mt][h];
            v += __shfl_xor_sync(0xffffffffu, v, 1);
            v += __shfl_xor_sync(0xffffffffu, v, 2);
            rs[mt][h] = 1.f / v;
        }
#pragma unroll
    for (int mt = 0; mt < 2; mt++)
#pragma unroll
        for (int h = 0; h < 2; h++) {
            int r = m0 + mt * 16 + h * 8 + g8;
            bf16* op = out + (size_t)(win * 256 + r) * CDIM + head * HD;
            float inv = rs[mt][h];
#pragma unroll
            for (int nto = 0; nto < 4; nto++)
                *(__nv_bfloat162*)(op + nto * 8 + (q << 1)) =
                    __floats2bfloat162_rn(o[mt][nto][h * 2 + 0] * inv,
                                          o[mt][nto][h * 2 + 1] * inv);
        }
}

// ---------------- tiled depthwise 3x3x3 conv + bias + exact GELU -------------------
// block = 128-channel group x 4x4x4 token tile; halo 6x6x6x128 bf16 in smem (55296 B)
#define CONV_SMEM_BYTES (216 * 128 * 2)
__global__ void __launch_bounds__(256)
conv_gelu_tiled(const bf16* __restrict__ hin, const float* __restrict__ wt,
                const float* __restrict__ cb, bf16* __restrict__ hout) {
    extern __shared__ bf16 hs[];   // [216][128]
    int cg = blockIdx.x;           // 0..5
    int tile = blockIdx.y;         // 0..1023
    int d0 = (tile >> 8) << 2;
    int h0 = ((tile >> 4) & 15) << 2;
    int w0 = (tile & 15) << 2;
    int tid = threadIdx.x;
    int c = tid & 127;
    int phalf = tid >> 7;          // 0..1
    int cbase = cg << 7;

#pragma unroll 4
    for (int i = 0; i < 108; i++) {
        int p = phalf + (i << 1);
        int pd = p / 36, rem = p - pd * 36;
        int ph = rem / 6, pw = rem - ph * 6;
        int gd = d0 - 1 + pd, gh = h0 - 1 + ph, gw = w0 - 1 + pw;
        bf16 v = __float2bfloat16(0.f);
        if ((unsigned)gd < 16u && (unsigned)gh < 64u && (unsigned)gw < 64u)
            v = hin[(size_t)((gd << 12) | (gh << 6) | gw) * HIDDEN + cbase + c];
        hs[p * 128 + c] = v;
    }
    float w[27];
#pragma unroll
    for (int k = 0; k < 27; k++) w[k] = wt[(cbase + c) * 27 + k];
    float bias = cb[cbase + c];
    __syncthreads();

#pragma unroll 2
    for (int i = 0; i < 32; i++) {
        int t = phalf + (i << 1);
        int td = t >> 4, th = (t >> 2) & 3, tw = t & 3;
        float acc = bias;
        int k = 0;
#pragma unroll
        for (int kd = 0; kd < 3; kd++)
#pragma unroll
            for (int kh = 0; kh < 3; kh++) {
                int pbase = (td + kd) * 36 + (th + kh) * 6 + tw;
#pragma unroll
                for (int kw = 0; kw < 3; kw++, k++)
                    acc += w[k] * __bfloat162float(hs[(pbase + kw) * 128 + c]);
            }
        float gl = 0.5f * acc * (1.f + erff(acc * 0.70710678118654752f));
        int n = ((d0 + td) << 12) | ((h0 + th) << 6) | (w0 + tw);
        hout[(size_t)n * HIDDEN + cbase + c] = __float2bfloat16(gl);
    }
}

// ---------------- launch ----------------
extern "C" void kernel_launch(void* const* d_in, const int* in_sizes, int n_in,
                              void* d_out, int out_size) {
    const float* x     = (const float*)d_in[0];
    const float* n1g   = (const float*)d_in[1];
    const float* n1b   = (const float*)d_in[2];
    const float* qkvw  = (const float*)d_in[3];
    const float* qkvb  = (const float*)d_in[4];
    const float* relb  = (const float*)d_in[5];
    const float* projw = (const float*)d_in[6];
    const float* projb = (const float*)d_in[7];
    const float* n2g   = (const float*)d_in[8];
    const float* n2b   = (const float*)d_in[9];
    const float* fc1A  = (const float*)d_in[10];
    const float* fc1Bw = (const float*)d_in[11];
    const float* fc1Bb = (const float*)d_in[12];
    const float* dww   = (const float*)d_in[13];
    const float* dwb   = (const float*)d_in[14];
    const float* fc2A  = (const float*)d_in[15];
    const float* fc2Bw = (const float*)d_in[16];
    const float* fc2Bb = (const float*)d_in[17];
    float* out = (float*)d_out;

    bf16 *p_ln, *p_qkv, *p_attn, *p_r1, *p_hid, *p_conv, *p_r2;
    bf16 *p_qkvwt, *p_projwt, *p_fc1At, *p_fc1Bt, *p_fc2At, *p_fc2Bt;
    float *p_x1;
    cudaGetSymbolAddress((void**)&p_ln,    g_ln);
    cudaGetSymbolAddress((void**)&p_qkv,   g_qkv);
    cudaGetSymbolAddress((void**)&p_attn,  g_attn);
    cudaGetSymbolAddress((void**)&p_x1,    g_x1);
    cudaGetSymbolAddress((void**)&p_r1,    g_r1);
    cudaGetSymbolAddress((void**)&p_hid,   g_hid);
    cudaGetSymbolAddress((void**)&p_conv,  g_conv);
    cudaGetSymbolAddress((void**)&p_r2,    g_r2);
    cudaGetSymbolAddress((void**)&p_qkvwt, g_qkvwt);
    cudaGetSymbolAddress((void**)&p_projwt, g_projwt);
    cudaGetSymbolAddress((void**)&p_fc1At, g_fc1At);
    cudaGetSymbolAddress((void**)&p_fc1Bt, g_fc1Bt);
    cudaGetSymbolAddress((void**)&p_fc2At, g_fc2At);
    cudaGetSymbolAddress((void**)&p_fc2Bt, g_fc2Bt);

    cudaFuncSetAttribute(attn_mma_kernel, cudaFuncAttributeMaxDynamicSharedMemorySize,
                         ATTN_SMEM_BYTES);
    cudaFuncSetAttribute(conv_gelu_tiled, cudaFuncAttributeMaxDynamicSharedMemorySize,
                         CONV_SMEM_BYTES);

    // 0. weight convert+transpose (bf16, [N][K])
    wconv_kernel<<<(192 * 576 + 255) / 256, 256>>>(qkvw,  p_qkvwt, 192, 576);
    wconv_kernel<<<(192 * 192 + 255) / 256, 256>>>(projw, p_projwt, 192, 192);
    wconv_kernel<<<(192 * 384 + 255) / 256, 256>>>(fc1A,  p_fc1At, 192, 384);
    wconv_kernel<<<(384 * 768 + 255) / 256, 256>>>(fc1Bw, p_fc1Bt, 384, 768);
    wconv_kernel<<<(768 * 96 + 255) / 256, 256>>>(fc2A,  p_fc2At, 768, 96);
    wconv_kernel<<<(96 * 192 + 255) / 256, 256>>>(fc2Bw, p_fc2Bt, 96, 192);

    // 1. LN1 + window permute (bf16 out)
    ln_kernel<true><<<NTOK / 8, 256>>>(x, n1g, n1b, p_ln);
    // 2. qkv = xw @ qkv_w + b   [65536 x 576], K=192  (bf16 out)
    mma_gemm<1, true><<<dim3(5, 512), 256>>>(p_ln, p_qkvwt, qkvb, nullptr, p_qkv, 576, 192);
    // 3. windowed attention (bf16)
    attn_mma_kernel<<<dim3(NHEADS, 256), 256, ATTN_SMEM_BYTES>>>(p_qkv, relb, p_attn);
    // 4. proj + inverse permute + residual -> x1 fp32
    mma_gemm<2, false><<<dim3(2, 512), 256>>>(p_attn, p_projwt, projb, x, p_x1, 192, 192);
    // 5. LN2 (bf16 out)
    ln_kernel<false><<<NTOK / 8, 256>>>(p_x1, n2g, n2b, p_ln);
    // 6. r1 = hn @ fc1_A   [65536 x 384], K=192 (bf16)
    mma_gemm<0, true><<<dim3(3, 512), 256>>>(p_ln, p_fc1At, nullptr, nullptr, p_r1, 384, 192);
    // 7. hid = r1 @ fc1_Bw + b   [65536 x 768], K=384 (bf16)
    mma_gemm<1, true><<<dim3(6, 512), 256>>>(p_r1, p_fc1Bt, fc1Bb, nullptr, p_hid, 768, 384);
    // 8. tiled depthwise conv3d + bias + GELU (bf16)
    conv_gelu_tiled<<<dim3(6, 1024), 256, CONV_SMEM_BYTES>>>(p_hid, dww, dwb, p_conv);
    // 9. r2 = conv @ fc2_A   [65536 x 96], K=768 (bf16)
    mma_gemm<0, true><<<dim3(1, 512), 256>>>(p_conv, p_fc2At, nullptr, nullptr, p_r2, 96, 768);
    // 10. out = x1 + r2 @ fc2_Bw + b   [65536 x 192], K=96 (fp32)
    mma_gemm<3, false><<<dim3(2, 512), 256>>>(p_r2, p_fc2Bt, fc2Bb, p_x1, out, 192, 96);
}

// round 10
// speedup vs baseline: 3.1071x; 1.0022x over previous
#include <cuda_runtime.h>
#include <cuda_bf16.h>
#include <math.h>

// Problem constants (B=1, D=16, H=64, W=64)
#define NTOK   65536
#define CDIM   192
#define NHEADS 6
#define HD     32
#define HIDDEN 768
#define RANK1  384
#define RANK2  96
#define ATTN_SCALE 0.17677669529663687f  // 32^-0.5

typedef __nv_bfloat16 bf16;

// ---------------- scratch (device globals; no runtime allocation) ----------------
__device__ bf16  g_ln[(size_t)NTOK * CDIM];
__device__ bf16  g_qkv[(size_t)NTOK * 576];
__device__ bf16  g_attn[(size_t)NTOK * CDIM];
__device__ float g_x1[(size_t)NTOK * CDIM];
__device__ bf16  g_r1[(size_t)NTOK * RANK1];
__device__ bf16  g_hid[(size_t)NTOK * HIDDEN];
__device__ bf16  g_conv[(size_t)NTOK * HIDDEN];
__device__ bf16  g_r2[(size_t)NTOK * RANK2];
// transposed bf16 weights [N][K]
__device__ bf16  g_qkvwt[576 * 192];
__device__ bf16  g_projwt[192 * 192];
__device__ bf16  g_fc1At[RANK1 * 192];
__device__ bf16  g_fc1Bt[HIDDEN * RANK1];
__device__ bf16  g_fc2At[RANK2 * HIDDEN];
__device__ bf16  g_fc2Bt[CDIM * RANK2];

// ---------------- helpers ----------------
__device__ __forceinline__ int token_to_wrow(int n) {
    int w = n & 63, h = (n >> 6) & 63, d = n >> 12;
    int win = ((d >> 2) << 6) | ((h >> 3) << 3) | (w >> 3);
    int t   = ((d & 3) << 6) | ((h & 7) << 3) | (w & 7);
    return (win << 8) | t;
}
__device__ __forceinline__ int wrow_to_token(int r) {
    int win = r >> 8, t = r & 255;
    int d = ((win >> 6) << 2) | (t >> 6);
    int h = (((win >> 3) & 7) << 3) | ((t >> 3) & 7);
    int w = ((win & 7) << 3) | (t & 7);
    return (d << 12) | (h << 6) | w;
}
__device__ __forceinline__ void cp16(void* smem, const void* gmem) {
    unsigned s = (unsigned)__cvta_generic_to_shared(smem);
    asm volatile("cp.async.cg.shared.global [%0], [%1], 16;\n" :: "r"(s), "l"(gmem));
}
__device__ __forceinline__ void cp16z(void* smem, const void* gmem) {
    unsigned s = (unsigned)__cvta_generic_to_shared(smem);
    asm volatile("cp.async.cg.shared.global [%0], [%1], 16, 0;\n" :: "r"(s), "l"(gmem));
}
__device__ __forceinline__ void ldsm4(unsigned* r, unsigned addr) {
    asm volatile("ldmatrix.sync.aligned.m8n8.x4.shared.b16 {%0,%1,%2,%3}, [%4];"
                 : "=r"(r[0]), "=r"(r[1]), "=r"(r[2]), "=r"(r[3]) : "r"(addr));
}
#define MMA_BF16(C, A, B)                                                      \
    asm volatile(                                                              \
        "mma.sync.aligned.m16n8k16.row.col.f32.bf16.bf16.f32 "                 \
        "{%0,%1,%2,%3},{%4,%5,%6,%7},{%8,%9},{%0,%1,%2,%3};\n"                 \
        : "+f"((C)[0]), "+f"((C)[1]), "+f"((C)[2]), "+f"((C)[3])               \
        : "r"((A)[0]), "r"((A)[1]), "r"((A)[2]), "r"((A)[3]),                  \
          "r"((B)[0]), "r"((B)[1]))

// ---------------- all-weights convert + transpose (one launch) ---------------------
// sizes: qkv 192x576, proj 192x192, fc1A 192x384, fc1B 384x768, fc2A 768x96, fc2B 96x192
__global__ void wconv_all(const float* s0, const float* s1, const float* s2,
                          const float* s3, const float* s4, const float* s5,
                          bf16* d0, bf16* d1, bf16* d2,
                          bf16* d3, bf16* d4, bf16* d5) {
    int idx = blockIdx.x * 256 + threadIdx.x;
    const float* src; bf16* dst; int K, N;
    if (idx < 110592)      { src = s0; dst = d0; K = 192; N = 576; }
    else if (idx < 147456) { src = s1; dst = d1; K = 192; N = 192; idx -= 110592; }
    else if (idx < 221184) { src = s2; dst = d2; K = 192; N = 384; idx -= 147456; }
    else if (idx < 516096) { src = s3; dst = d3; K = 384; N = 768; idx -= 221184; }
    else if (idx < 589824) { src = s4; dst = d4; K = 768; N = 96;  idx -= 516096; }
    else if (idx < 608256) { src = s5; dst = d5; K = 96;  N = 192; idx -= 589824; }
    else return;
    int k = idx / N, n = idx - k * N;
    dst[n * K + k] = __float2bfloat16(src[idx]);
}

// ---------------- LayerNorm: warp per token -> bf16 out ----------------
template <bool PERM>
__global__ void __launch_bounds__(256)
ln_kernel(const float* __restrict__ x, const float* __restrict__ g,
          const float* __restrict__ b, bf16* __restrict__ out) {
    int lane = threadIdx.x & 31, wid = threadIdx.x >> 5;
    int n = (blockIdx.x << 3) + wid;
    const float* xp = x + (size_t)n * CDIM;
    float v[6];
#pragma unroll
    for (int i = 0; i < 6; i++) v[i] = xp[lane + (i << 5)];
    float s = 0.f, s2 = 0.f;
#pragma unroll
    for (int i = 0; i < 6; i++) { s += v[i]; s2 += v[i] * v[i]; }
#pragma unroll
    for (int o = 16; o; o >>= 1) {
        s  += __shfl_xor_sync(0xffffffffu, s,  o);
        s2 += __shfl_xor_sync(0xffffffffu, s2, o);
    }
    float mean = s * (1.0f / CDIM);
    float rstd = rsqrtf(s2 * (1.0f / CDIM) - mean * mean + 1e-5f);
    int orow = PERM ? token_to_wrow(n) : n;
    bf16* op = out + (size_t)orow * CDIM;
#pragma unroll
    for (int i = 0; i < 6; i++) {
        int c = lane + (i << 5);
        op[c] = __float2bfloat16((v[i] - mean) * rstd * __ldg(g + c) + __ldg(b + c));
    }
}

// ---------------- BF16 GEMM 128x128x32, 3-stage, ldmatrix fragment loads -----------
template <int MODE, bool OUTBF>
__global__ void __launch_bounds__(256)
mma_gemm(const bf16* __restrict__ A, const bf16* __restrict__ B,
         const float* __restrict__ bias, const float* __restrict__ resid,
         void* __restrict__ Cv, int N, int K) {
    __shared__ bf16 As[3][128][40];
    __shared__ bf16 Bs[3][128][40];
    int tid = threadIdx.x, lane = tid & 31, warp = tid >> 5;
    int wm = warp & 1, wn = warp >> 1;
    int bm = blockIdx.y << 7, bn = blockIdx.x << 7;
    int q = lane & 3, g8 = lane >> 2;

    float c[4][4][4];
#pragma unroll
    for (int mt = 0; mt < 4; mt++)
#pragma unroll
        for (int nt = 0; nt < 4; nt++)
#pragma unroll
            for (int r = 0; r < 4; r++) c[mt][nt][r] = 0.f;

    int KT = K >> 5;

    int r0 = tid >> 2,          o0 = (tid & 3) << 3;
    int r1 = (tid + 256) >> 2,  o1 = ((tid + 256) & 3) << 3;

    // ldmatrix addressing: row = base + (lane&15), k-col = kk + ((lane>>4)<<3)
    unsigned asm_base = (unsigned)__cvta_generic_to_shared(&As[0][0][0]);
    unsigned bsm_base = (unsigned)__cvta_generic_to_shared(&Bs[0][0][0]);
    int lrow = lane & 15, lcol = (lane >> 4) << 3;
    unsigned a_off = ((wm * 64 + lrow) * 40 + lcol) * 2;
    unsigned b_off = ((wn * 32 + lrow) * 40 + lcol) * 2;

#define COPY_STAGE(S, K0)                                                        \
    do {                                                                         \
        cp16(&As[S][r0][o0], A + (size_t)(bm + r0) * K + (K0) + o0);             \
        cp16(&As[S][r1][o1], A + (size_t)(bm + r1) * K + (K0) + o1);             \
        if (bn + r0 < N) cp16(&Bs[S][r0][o0], B + (size_t)(bn + r0) * K + (K0) + o0); \
        else             cp16z(&Bs[S][r0][o0], B);                               \
        if (bn + r1 < N) cp16(&Bs[S][r1][o1], B + (size_t)(bn + r1) * K + (K0) + o1); \
        else             cp16z(&Bs[S][r1][o1], B);                               \
    } while (0)

    COPY_STAGE(0, 0);
    asm volatile("cp.async.commit_group;\n");
    COPY_STAGE(1, 32);
    asm volatile("cp.async.commit_group;\n");

    int s = 0;
    for (int kt = 0; kt < KT; kt++) {
        asm volatile("cp.async.wait_group 1;\n");
        __syncthreads();
        int sc = s + 2; if (sc >= 3) sc -= 3;
        if (kt + 2 < KT) COPY_STAGE(sc, (kt + 2) << 5);
        asm volatile("cp.async.commit_group;\n");
        unsigned aS = asm_base + s * (128 * 40 * 2) + a_off;
        unsigned bS = bsm_base + s * (128 * 40 * 2) + b_off;
#pragma unroll
        for (int kk = 0; kk < 32; kk += 16) {
            unsigned af[4][4], bf[4][4];
#pragma unroll
            for (int mt = 0; mt < 4; mt++)
                ldsm4(af[mt], aS + (mt * 16 * 40 + kk) * 2);
#pragma unroll
            for (int ntp = 0; ntp < 2; ntp++)
                ldsm4(bf[ntp * 2], bS + (ntp * 16 * 40 + kk) * 2);
            // bf[2p][0]=n..n+7@k, bf[2p][1]=n+8..15@k, bf[2p][2]=n..7@k+8, bf[2p][3]=n+8..@k+8
#pragma unroll
            for (int mt = 0; mt < 4; mt++)
#pragma unroll
                for (int ntp = 0; ntp < 2; ntp++) {
                    unsigned b0[2] = { bf[ntp * 2][0], bf[ntp * 2][2] };
                    unsigned b1[2] = { bf[ntp * 2][1], bf[ntp * 2][3] };
                    MMA_BF16(c[mt][ntp * 2 + 0], af[mt], b0);
                    MMA_BF16(c[mt][ntp * 2 + 1], af[mt], b1);
                }
        }
        if (++s >= 3) s = 0;
    }
#undef COPY_STAGE

#pragma unroll
    for (int mt = 0; mt < 4; mt++) {
        int row0 = bm + wm * 64 + mt * 16 + g8;
#pragma unroll
        for (int half = 0; half < 2; half++) {
            int row = row0 + half * 8;
            int orow = (MODE == 2) ? wrow_to_token(row) : row;
#pragma unroll
            for (int nt = 0; nt < 4; nt++) {
                int col = bn + wn * 32 + nt * 8 + (q << 1);
                if (col < N) {
                    float v0 = c[mt][nt][half * 2 + 0];
                    float v1 = c[mt][nt][half * 2 + 1];
                    if (MODE >= 1) { v0 += bias[col]; v1 += bias[col + 1]; }
                    if (MODE >= 2) {
                        float2 rr = *(const float2*)(resid + (size_t)orow * N + col);
                        v0 += rr.x; v1 += rr.y;
                    }
                    if (OUTBF) {
                        *( __nv_bfloat162*)((bf16*)Cv + (size_t)orow * N + col) =
                            __floats2bfloat162_rn(v0, v1);
                    } else {
                        *(float2*)((float*)Cv + (size_t)orow * N + col) =
                            make_float2(v0, v1);
                    }
                }
            }
        }
    }
}

// ---------------- bf16 tensor-core windowed attention ------------------------------
#define ATTN_SMEM_BYTES 65184
__global__ void __launch_bounds__(256)
attn_mma_kernel(const bf16* __restrict__ qkv, const float* __restrict__ rel_bias,
                bf16* __restrict__ out) {
    extern __shared__ char smc[];
    bf16*  Ks  = (bf16*)smc;             // [256][40]
    bf16*  Vt  = (bf16*)(smc + 20480);   // [32][264]
    bf16*  Ps  = (bf16*)(smc + 37376);   // [256][40]  (Q staging, then P)
    float* bsh = (float*)(smc + 57856);  // [1575]
    int*   sid = (int*)(smc + 64160);    // [256]

    int head = blockIdx.x, win = blockIdx.y;
    int tid = threadIdx.x, lane = tid & 31, warp = tid >> 5;
    int q = lane & 3, g8 = lane >> 2;
    int m0 = warp << 5;

    const bf16* base = qkv + (size_t)win * 256 * 576 + head * HD;
    for (int idx = tid; idx < 256 * 32; idx += 256) {
        int r = idx >> 5, d = idx & 31;
        const bf16* p = base + (size_t)r * 576 + d;
        Ks[r * 40 + d]  = p[192];
        Vt[d * 264 + r] = p[384];
    }
#pragma unroll 4
    for (int i = 0; i < 32; i++)
        Ps[(m0 + i) * 40 + lane] = base[(size_t)(m0 + i) * 576 + lane];
    for (int i = tid; i < 1575; i += 256) bsh[i] = rel_bias[i * 6 + head];
    {
        int t = tid;
        int gd = ((win >> 6) << 2) | (t >> 6);
        int gh = (((win >> 3) & 7) << 3) | ((t >> 3) & 7);
        int gw = ((win & 7) << 3) | (t & 7);
        sid[t] = ((((gd + 2) & 15) >> 2) << 6) | ((((gh + 4) & 63) >> 3) << 3) |
                 (((gw + 4) & 63) >> 3);
    }
    __syncthreads();

    unsigned qf[2][2][4];
#pragma unroll
    for (int mt = 0; mt < 2; mt++)
#pragma unroll
        for (int ks = 0; ks < 2; ks++) {
            int m = m0 + mt * 16 + g8, k = ks * 16 + 2 * q;
            qf[mt][ks][0] = *(const unsigned*)&Ps[m * 40 + k];
            qf[mt][ks][1] = *(const unsigned*)&Ps[(m + 8) * 40 + k];
            qf[mt][ks][2] = *(const unsigned*)&Ps[m * 40 + k + 8];
            qf[mt][ks][3] = *(const unsigned*)&Ps[(m + 8) * 40 + k + 8];
        }
    int rd_[2][2], rh_[2][2], rw_[2][2], msid[2][2];
#pragma unroll
    for (int mt = 0; mt < 2; mt++)
#pragma unroll
        for (int h = 0; h < 2; h++) {
            int r = m0 + mt * 16 + h * 8 + g8;
            rd_[mt][h] = r >> 6; rh_[mt][h] = (r >> 3) & 7; rw_[mt][h] = r & 7;
            msid[mt][h] = sid[r];
        }
    __syncwarp();

    float o[2][4][4];
#pragma unroll
    for (int mt = 0; mt < 2; mt++)
#pragma unroll
        for (int nt = 0; nt < 4; nt++)
#pragma unroll
            for (int e = 0; e < 4; e++) o[mt][nt][e] = 0.f;
    float rs[2][2] = {{0.f, 0.f}, {0.f, 0.f}};

    for (int ck = 0; ck < 256; ck += 32) {
        float s[2][4][4];
#pragma unroll
        for (int mt = 0; mt < 2; mt++)
#pragma unroll
            for (int nt = 0; nt < 4; nt++)
#pragma unroll
                for (int e = 0; e < 4; e++) s[mt][nt][e] = 0.f;
#pragma unroll
        for (int ks = 0; ks < 2; ks++) {
            unsigned kf[4][2];
#pragma unroll
            for (int nt = 0; nt < 4; nt++) {
                int n = ck + nt * 8 + g8;
                kf[nt][0] = *(const unsigned*)&Ks[n * 40 + ks * 16 + 2 * q];
                kf[nt][1] = *(const unsigned*)&Ks[n * 40 + ks * 16 + 2 * q + 8];
            }
#pragma unroll
            for (int mt = 0; mt < 2; mt++)
#pragma unroll
                for (int nt = 0; nt < 4; nt++)
                    MMA_BF16(s[mt][nt], qf[mt][ks], kf[nt]);
        }
#pragma unroll
        for (int nt = 0; nt < 4; nt++) {
            int cc = ck + nt * 8;
            int cd = cc >> 6, ch = (cc >> 3) & 7;
            int sc = (q >= 2) ? sid[cc + 4] : sid[cc];
#pragma unroll
            for (int mt = 0; mt < 2; mt++)
#pragma unroll
                for (int h = 0; h < 2; h++) {
                    int bidx = (rd_[mt][h] - cd + 3) * 225 +
                               (rh_[mt][h] - ch + 7) * 15 + rw_[mt][h] + 7 - (q << 1);
                    float p0, p1;
                    if (msid[mt][h] == sc) {
                        p0 = __expf(fmaf(s[mt][nt][h * 2 + 0], ATTN_SCALE, bsh[bidx]));
                        p1 = __expf(fmaf(s[mt][nt][h * 2 + 1], ATTN_SCALE, bsh[bidx - 1]));
                    } else { p0 = 0.f; p1 = 0.f; }
                    __nv_bfloat162 pp = __floats2bfloat162_rn(p0, p1);
                    rs[mt][h] += __bfloat162float(pp.x) + __bfloat162float(pp.y);
                    int r = m0 + mt * 16 + h * 8 + g8;
                    *(__nv_bfloat162*)&Ps[r * 40 + nt * 8 + (q << 1)] = pp;
                }
        }
        __syncwarp();
#pragma unroll
        for (int ks = 0; ks < 2; ks++) {
            unsigned vf[4][2], pf[2][4];
#pragma unroll
            for (int nto = 0; nto < 4; nto++) {
                int d = nto * 8 + g8;
                vf[nto][0] = *(const unsigned*)&Vt[d * 264 + ck + ks * 16 + 2 * q];
                vf[nto][1] = *(const unsigned*)&Vt[d * 264 + ck + ks * 16 + 2 * q + 8];
            }
#pragma unroll
            for (int mt = 0; mt < 2; mt++) {
                int m = m0 + mt * 16 + g8, k = ks * 16 + 2 * q;
                pf[mt][0] = *(const unsigned*)&Ps[m * 40 + k];
                pf[mt][1] = *(const unsigned*)&Ps[(m + 8) * 40 + k];
                pf[mt][2] = *(const unsigned*)&Ps[m * 40 + k + 8];
                pf[mt][3] = *(const unsigned*)&Ps[(m + 8) * 40 + k + 8];
            }
#pragma unroll
            for (int mt = 0; mt < 2; mt++)
#pragma unroll
                for (int nto = 0; nto < 4; nto++)
                    MMA_BF16(o[mt][nto], pf[mt], vf[nto]);
        }
        __syncwarp();
    }

#pragma unroll
    for (int mt = 0; mt < 2; mt++)
#pragma unroll
        for (int h = 0; h < 2; h++) {
            float v = rs[mt][h];
            v += __shfl_xor_sync(0xffffffffu, v, 1);
            v += __shfl_xor_sync(0xffffffffu, v, 2);
            rs[mt][h] = 1.f / v;
        }
#pragma unroll
    for (int mt = 0; mt < 2; mt++)
#pragma unroll
        for (int h = 0; h < 2; h++) {
            int r = m0 + mt * 16 + h * 8 + g8;
            bf16* op = out + (size_t)(win * 256 + r) * CDIM + head * HD;
            float inv = rs[mt][h];
#pragma unroll
            for (int nto = 0; nto < 4; nto++)
                *(__nv_bfloat162*)(op + nto * 8 + (q << 1)) =
                    __floats2bfloat162_rn(o[mt][nto][h * 2 + 0] * inv,
                                          o[mt][nto][h * 2 + 1] * inv);
        }
}

// ---------------- tiled depthwise 3x3x3 conv + bias + exact GELU -------------------
#define CONV_SMEM_BYTES (216 * 128 * 2)
__global__ void __launch_bounds__(256)
conv_gelu_tiled(const bf16* __restrict__ hin, const float* __restrict__ wt,
                const float* __restrict__ cb, bf16* __restrict__ hout) {
    extern __shared__ bf16 hs[];   // [216][128]
    int cg = blockIdx.x;
    int tile = blockIdx.y;
    int d0 = (tile >> 8) << 2;
    int h0 = ((tile >> 4) & 15) << 2;
    int w0 = (tile & 15) << 2;
    int tid = threadIdx.x;
    int c = tid & 127;
    int phalf = tid >> 7;
    int cbase = cg << 7;

#pragma unroll 4
    for (int i = 0; i < 108; i++) {
        int p = phalf + (i << 1);
        int pd = p / 36, rem = p - pd * 36;
        int ph = rem / 6, pw = rem - ph * 6;
        int gd = d0 - 1 + pd, gh = h0 - 1 + ph, gw = w0 - 1 + pw;
        bf16 v = __float2bfloat16(0.f);
        if ((unsigned)gd < 16u && (unsigned)gh < 64u && (unsigned)gw < 64u)
            v = hin[(size_t)((gd << 12) | (gh << 6) | gw) * HIDDEN + cbase + c];
        hs[p * 128 + c] = v;
    }
    float w[27];
#pragma unroll
    for (int k = 0; k < 27; k++) w[k] = wt[(cbase + c) * 27 + k];
    float bias = cb[cbase + c];
    __syncthreads();

#pragma unroll 2
    for (int i = 0; i < 32; i++) {
        int t = phalf + (i << 1);
        int td = t >> 4, th = (t >> 2) & 3, tw = t & 3;
        float acc = bias;
        int k = 0;
#pragma unroll
        for (int kd = 0; kd < 3; kd++)
#pragma unroll
            for (int kh = 0; kh < 3; kh++) {
                int pbase = (td + kd) * 36 + (th + kh) * 6 + tw;
#pragma unroll
                for (int kw = 0; kw < 3; kw++, k++)
                    acc += w[k] * __bfloat162float(hs[(pbase + kw) * 128 + c]);
            }
        float gl = 0.5f * acc * (1.f + erff(acc * 0.70710678118654752f));
        int n = ((d0 + td) << 12) | ((h0 + th) << 6) | (w0 + tw);
        hout[(size_t)n * HIDDEN + cbase + c] = __float2bfloat16(gl);
    }
}

// ---------------- launch ----------------
extern "C" void kernel_launch(void* const* d_in, const int* in_sizes, int n_in,
                              void* d_out, int out_size) {
    const float* x     = (const float*)d_in[0];
    const float* n1g   = (const float*)d_in[1];
    const float* n1b   = (const float*)d_in[2];
    const float* qkvw  = (const float*)d_in[3];
    const float* qkvb  = (const float*)d_in[4];
    const float* relb  = (const float*)d_in[5];
    const float* projw = (const float*)d_in[6];
    const float* projb = (const float*)d_in[7];
    const float* n2g   = (const float*)d_in[8];
    const float* n2b   = (const float*)d_in[9];
    const float* fc1A  = (const float*)d_in[10];
    const float* fc1Bw = (const float*)d_in[11];
    const float* fc1Bb = (const float*)d_in[12];
    const float* dww   = (const float*)d_in[13];
    const float* dwb   = (const float*)d_in[14];
    const float* fc2A  = (const float*)d_in[15];
    const float* fc2Bw = (const float*)d_in[16];
    const float* fc2Bb = (const float*)d_in[17];
    float* out = (float*)d_out;

    bf16 *p_ln, *p_qkv, *p_attn, *p_r1, *p_hid, *p_conv, *p_r2;
    bf16 *p_qkvwt, *p_projwt, *p_fc1At, *p_fc1Bt, *p_fc2At, *p_fc2Bt;
    float *p_x1;
    cudaGetSymbolAddress((void**)&p_ln,    g_ln);
    cudaGetSymbolAddress((void**)&p_qkv,   g_qkv);
    cudaGetSymbolAddress((void**)&p_attn,  g_attn);
    cudaGetSymbolAddress((void**)&p_x1,    g_x1);
    cudaGetSymbolAddress((void**)&p_r1,    g_r1);
    cudaGetSymbolAddress((void**)&p_hid,   g_hid);
    cudaGetSymbolAddress((void**)&p_conv,  g_conv);
    cudaGetSymbolAddress((void**)&p_r2,    g_r2);
    cudaGetSymbolAddress((void**)&p_qkvwt, g_qkvwt);
    cudaGetSymbolAddress((void**)&p_projwt, g_projwt);
    cudaGetSymbolAddress((void**)&p_fc1At, g_fc1At);
    cudaGetSymbolAddress((void**)&p_fc1Bt, g_fc1Bt);
    cudaGetSymbolAddress((void**)&p_fc2At, g_fc2At);
    cudaGetSymbolAddress((void**)&p_fc2Bt, g_fc2Bt);

    cudaFuncSetAttribute(attn_mma_kernel, cudaFuncAttributeMaxDynamicSharedMemorySize,
                         ATTN_SMEM_BYTES);
    cudaFuncSetAttribute(conv_gelu_tiled, cudaFuncAttributeMaxDynamicSharedMemorySize,
                         CONV_SMEM_BYTES);

    // 0. all weights convert+transpose (one launch)
    wconv_all<<<(608256 + 255) / 256, 256>>>(qkvw, projw, fc1A, fc1Bw, fc2A, fc2Bw,
                                             p_qkvwt, p_projwt, p_fc1At, p_fc1Bt,
                                             p_fc2At, p_fc2Bt);

    // 1. LN1 + window permute (bf16 out)
    ln_kernel<true><<<NTOK / 8, 256>>>(x, n1g, n1b, p_ln);
    // 2. qkv = xw @ qkv_w + b   [65536 x 576], K=192  (bf16 out)
    mma_gemm<1, true><<<dim3(5, 512), 256>>>(p_ln, p_qkvwt, qkvb, nullptr, p_qkv, 576, 192);
    // 3. windowed attention (bf16)
    attn_mma_kernel<<<dim3(NHEADS, 256), 256, ATTN_SMEM_BYTES>>>(p_qkv, relb, p_attn);
    // 4. proj + inverse permute + residual -> x1 fp32
    mma_gemm<2, false><<<dim3(2, 512), 256>>>(p_attn, p_projwt, projb, x, p_x1, 192, 192);
    // 5. LN2 (bf16 out)
    ln_kernel<false><<<NTOK / 8, 256>>>(p_x1, n2g, n2b, p_ln);
    // 6. r1 = hn @ fc1_A   [65536 x 384], K=192 (bf16)
    mma_gemm<0, true><<<dim3(3, 512), 256>>>(p_ln, p_fc1At, nullptr, nullptr, p_r1, 384, 192);
    // 7. hid = r1 @ fc1_Bw + b   [65536 x 768], K=384 (bf16)
    mma_gemm<1, true><<<dim3(6, 512), 256>>>(p_r1, p_fc1Bt, fc1Bb, nullptr, p_hid, 768, 384);
    // 8. tiled depthwise conv3d + bias + GELU (bf16)
    conv_gelu_tiled<<<dim3(6, 1024), 256, CONV_SMEM_BYTES>>>(p_hid, dww, dwb, p_conv);
    // 9. r2 = conv @ fc2_A   [65536 x 96], K=768 (bf16)
    mma_gemm<0, true><<<dim3(1, 512), 256>>>(p_conv, p_fc2At, nullptr, nullptr, p_r2, 96, 768);
    // 10. out = x1 + r2 @ fc2_Bw + b   [65536 x 192], K=96 (fp32)
    mma_gemm<3, false><<<dim3(2, 512), 256>>>(p_r2, p_fc2Bt, fc2Bb, p_x1, out, 192, 96);
}

// round 11
// speedup vs baseline: 3.3149x; 1.0669x over previous
#include <cuda_runtime.h>
#include <cuda_bf16.h>
#include <math.h>

// Problem constants (B=1, D=16, H=64, W=64)
#define NTOK   65536
#define CDIM   192
#define NHEADS 6
#define HD     32
#define HIDDEN 768
#define RANK1  384
#define RANK2  96
#define ATTN_SCALE 0.17677669529663687f  // 32^-0.5

typedef __nv_bfloat16 bf16;

// ---------------- scratch (device globals; no runtime allocation) ----------------
__device__ bf16  g_ln[(size_t)NTOK * CDIM];
__device__ bf16  g_qkv[(size_t)NTOK * 576];
__device__ bf16  g_attn[(size_t)NTOK * CDIM];
__device__ float g_x1[(size_t)NTOK * CDIM];
__device__ bf16  g_r1[(size_t)NTOK * RANK1];
__device__ bf16  g_hid[(size_t)NTOK * HIDDEN];
__device__ bf16  g_conv[(size_t)NTOK * HIDDEN];
__device__ bf16  g_r2[(size_t)NTOK * 128];      // padded K (cols 96..127 = 0)
// transposed bf16 weights [N][K]
__device__ bf16  g_qkvwt[576 * 192];
__device__ bf16  g_projwt[192 * 192];
__device__ bf16  g_fc1At[RANK1 * 192];
__device__ bf16  g_fc1Bt[HIDDEN * RANK1];
__device__ bf16  g_fc2At[128 * HIDDEN];         // padded N rows 96..127 = 0
__device__ bf16  g_fc2Bt[CDIM * 128];           // padded K cols 96..127 = 0

// ---------------- helpers ----------------
__device__ __forceinline__ int token_to_wrow(int n) {
    int w = n & 63, h = (n >> 6) & 63, d = n >> 12;
    int win = ((d >> 2) << 6) | ((h >> 3) << 3) | (w >> 3);
    int t   = ((d & 3) << 6) | ((h & 7) << 3) | (w & 7);
    return (win << 8) | t;
}
__device__ __forceinline__ int wrow_to_token(int r) {
    int win = r >> 8, t = r & 255;
    int d = ((win >> 6) << 2) | (t >> 6);
    int h = (((win >> 3) & 7) << 3) | ((t >> 3) & 7);
    int w = ((win & 7) << 3) | (t & 7);
    return (d << 12) | (h << 6) | w;
}
__device__ __forceinline__ void cp16(void* smem, const void* gmem) {
    unsigned s = (unsigned)__cvta_generic_to_shared(smem);
    asm volatile("cp.async.cg.shared.global [%0], [%1], 16;\n" :: "r"(s), "l"(gmem));
}
__device__ __forceinline__ void cp16z(void* smem, const void* gmem) {
    unsigned s = (unsigned)__cvta_generic_to_shared(smem);
    asm volatile("cp.async.cg.shared.global [%0], [%1], 16, 0;\n" :: "r"(s), "l"(gmem));
}
__device__ __forceinline__ void ldsm4(unsigned* r, unsigned addr) {
    asm volatile("ldmatrix.sync.aligned.m8n8.x4.shared.b16 {%0,%1,%2,%3}, [%4];"
                 : "=r"(r[0]), "=r"(r[1]), "=r"(r[2]), "=r"(r[3]) : "r"(addr));
}
#define MMA_BF16(C, A, B)                                                      \
    asm volatile(                                                              \
        "mma.sync.aligned.m16n8k16.row.col.f32.bf16.bf16.f32 "                 \
        "{%0,%1,%2,%3},{%4,%5,%6,%7},{%8,%9},{%0,%1,%2,%3};\n"                 \
        : "+f"((C)[0]), "+f"((C)[1]), "+f"((C)[2]), "+f"((C)[3])               \
        : "r"((A)[0]), "r"((A)[1]), "r"((A)[2]), "r"((A)[3]),                  \
          "r"((B)[0]), "r"((B)[1]))

// ---------------- all-weights convert + transpose (one launch, with padding) -------
__global__ void wconv_all(const float* s0, const float* s1, const float* s2,
                          const float* s3, const float* s4, const float* s5,
                          bf16* d0, bf16* d1, bf16* d2,
                          bf16* d3, bf16* d4, bf16* d5) {
    int idx = blockIdx.x * 256 + threadIdx.x;
    if (idx < 110592) {                 // qkv [192][576] -> [576][192]
        int k = idx / 576, n = idx - k * 576;
        d0[n * 192 + k] = __float2bfloat16(s0[idx]);
    } else if (idx < 147456) {          // proj [192][192] -> [192][192]
        idx -= 110592;
        int k = idx / 192, n = idx - k * 192;
        d1[n * 192 + k] = __float2bfloat16(s1[idx]);
    } else if (idx < 221184) {          // fc1A [192][384] -> [384][192]
        idx -= 147456;
        int k = idx / 384, n = idx - k * 384;
        d2[n * 192 + k] = __float2bfloat16(s2[idx]);
    } else if (idx < 516096) {          // fc1B [384][768] -> [768][384]
        idx -= 221184;
        int k = idx / 768, n = idx - k * 768;
        d3[n * 384 + k] = __float2bfloat16(s3[idx]);
    } else if (idx < 614400) {          // fc2A [768][96] -> [128][768] (pad n)
        idx -= 516096;
        int n = idx / 768, k = idx - n * 768;
        d4[idx] = (n < 96) ? __float2bfloat16(s4[k * 96 + n]) : __float2bfloat16(0.f);
    } else if (idx < 638976) {          // fc2B [96][192] -> [192][128] (pad k)
        idx -= 614400;
        int n = idx / 128, k = idx - n * 128;
        d5[idx] = (k < 96) ? __float2bfloat16(s5[k * 192 + n]) : __float2bfloat16(0.f);
    }
}

// ---------------- LayerNorm: warp per token -> bf16 out ----------------
template <bool PERM>
__global__ void __launch_bounds__(256)
ln_kernel(const float* __restrict__ x, const float* __restrict__ g,
          const float* __restrict__ b, bf16* __restrict__ out) {
    int lane = threadIdx.x & 31, wid = threadIdx.x >> 5;
    int n = (blockIdx.x << 3) + wid;
    const float* xp = x + (size_t)n * CDIM;
    float v[6];
#pragma unroll
    for (int i = 0; i < 6; i++) v[i] = xp[lane + (i << 5)];
    float s = 0.f, s2 = 0.f;
#pragma unroll
    for (int i = 0; i < 6; i++) { s += v[i]; s2 += v[i] * v[i]; }
#pragma unroll
    for (int o = 16; o; o >>= 1) {
        s  += __shfl_xor_sync(0xffffffffu, s,  o);
        s2 += __shfl_xor_sync(0xffffffffu, s2, o);
    }
    float mean = s * (1.0f / CDIM);
    float rstd = rsqrtf(s2 * (1.0f / CDIM) - mean * mean + 1e-5f);
    int orow = PERM ? token_to_wrow(n) : n;
    bf16* op = out + (size_t)orow * CDIM;
#pragma unroll
    for (int i = 0; i < 6; i++) {
        int c = lane + (i << 5);
        op[c] = __float2bfloat16((v[i] - mean) * rstd * __ldg(g + c) + __ldg(b + c));
    }
}

// ---------------- BF16 GEMM 128x128x64, 2-stage, ldmatrix, dynamic smem ------------
// A [M][K] bf16; B [N][K] bf16. K must be a multiple of 64.
// smem: As[2][128][72] then Bs[2][128][72]  (73728 B total)
#define GEMM_SMEM_BYTES (2 * 2 * 128 * 72 * 2)
#define ST_STRIDE (128 * 72)     // halves per stage per array
template <int MODE, bool OUTBF>
__global__ void __launch_bounds__(256)
mma_gemm(const bf16* __restrict__ A, const bf16* __restrict__ B,
         const float* __restrict__ bias, const float* __restrict__ resid,
         void* __restrict__ Cv, int N, int K) {
    extern __shared__ bf16 gsm[];
    bf16* As = gsm;                       // [2][128][72]
    bf16* Bs = gsm + 2 * ST_STRIDE;       // [2][128][72]
    int tid = threadIdx.x, lane = tid & 31, warp = tid >> 5;
    int wm = warp & 1, wn = warp >> 1;
    int bm = blockIdx.y << 7, bn = blockIdx.x << 7;
    int q = lane & 3, g8 = lane >> 2;

    float c[4][4][4];
#pragma unroll
    for (int mt = 0; mt < 4; mt++)
#pragma unroll
        for (int nt = 0; nt < 4; nt++)
#pragma unroll
            for (int r = 0; r < 4; r++) c[mt][nt][r] = 0.f;

    int KT = K >> 6;

    unsigned asm_base = (unsigned)__cvta_generic_to_shared(As);
    unsigned bsm_base = (unsigned)__cvta_generic_to_shared(Bs);
    int lrow = lane & 15, lcol = (lane >> 4) << 3;
    unsigned a_off = ((wm * 64 + lrow) * 72 + lcol) * 2;
    unsigned b_off = ((wn * 32 + lrow) * 72 + lcol) * 2;

    // copy: 1024 cp16 per array per stage -> 4 A-chunks + 4 B-chunks per thread
#define COPY_STAGE(S, K0)                                                         \
    do {                                                                          \
        _Pragma("unroll")                                                         \
        for (int cc = 0; cc < 4; cc++) {                                          \
            int id = tid + (cc << 8);                                             \
            int r = id >> 3, o = (id & 7) << 3;                                   \
            cp16(&As[(S) * ST_STRIDE + r * 72 + o],                               \
                 A + (size_t)(bm + r) * K + (K0) + o);                            \
            if (bn + r < N)                                                       \
                cp16(&Bs[(S) * ST_STRIDE + r * 72 + o],                           \
                     B + (size_t)(bn + r) * K + (K0) + o);                        \
            else                                                                  \
                cp16z(&Bs[(S) * ST_STRIDE + r * 72 + o], B);                      \
        }                                                                         \
    } while (0)

    COPY_STAGE(0, 0);
    asm volatile("cp.async.commit_group;\n");

    for (int kt = 0; kt < KT; kt++) {
        asm volatile("cp.async.wait_group 0;\n");
        __syncthreads();
        if (kt + 1 < KT) COPY_STAGE((kt + 1) & 1, (kt + 1) << 6);
        asm volatile("cp.async.commit_group;\n");
        int s = kt & 1;
        unsigned aS = asm_base + s * (ST_STRIDE * 2) + a_off;
        unsigned bS = bsm_base + s * (ST_STRIDE * 2) + b_off;
#pragma unroll
        for (int kk = 0; kk < 64; kk += 16) {
            unsigned af[4][4], bf[4][4];
#pragma unroll
            for (int mt = 0; mt < 4; mt++)
                ldsm4(af[mt], aS + (mt * 16 * 72 + kk) * 2);
#pragma unroll
            for (int ntp = 0; ntp < 2; ntp++)
                ldsm4(bf[ntp * 2], bS + (ntp * 16 * 72 + kk) * 2);
#pragma unroll
            for (int mt = 0; mt < 4; mt++)
#pragma unroll
                for (int ntp = 0; ntp < 2; ntp++) {
                    unsigned b0[2] = { bf[ntp * 2][0], bf[ntp * 2][2] };
                    unsigned b1[2] = { bf[ntp * 2][1], bf[ntp * 2][3] };
                    MMA_BF16(c[mt][ntp * 2 + 0], af[mt], b0);
                    MMA_BF16(c[mt][ntp * 2 + 1], af[mt], b1);
                }
        }
    }
#undef COPY_STAGE

#pragma unroll
    for (int mt = 0; mt < 4; mt++) {
        int row0 = bm + wm * 64 + mt * 16 + g8;
#pragma unroll
        for (int half = 0; half < 2; half++) {
            int row = row0 + half * 8;
            int orow = (MODE == 2) ? wrow_to_token(row) : row;
#pragma unroll
            for (int nt = 0; nt < 4; nt++) {
                int col = bn + wn * 32 + nt * 8 + (q << 1);
                if (col < N) {
                    float v0 = c[mt][nt][half * 2 + 0];
                    float v1 = c[mt][nt][half * 2 + 1];
                    if (MODE >= 1) { v0 += bias[col]; v1 += bias[col + 1]; }
                    if (MODE >= 2) {
                        float2 rr = *(const float2*)(resid + (size_t)orow * N + col);
                        v0 += rr.x; v1 += rr.y;
                    }
                    if (OUTBF) {
                        *( __nv_bfloat162*)((bf16*)Cv + (size_t)orow * N + col) =
                            __floats2bfloat162_rn(v0, v1);
                    } else {
                        *(float2*)((float*)Cv + (size_t)orow * N + col) =
                            make_float2(v0, v1);
                    }
                }
            }
        }
    }
}

// ---------------- bf16 tensor-core windowed attention ------------------------------
#define ATTN_SMEM_BYTES 65184
__global__ void __launch_bounds__(256)
attn_mma_kernel(const bf16* __restrict__ qkv, const float* __restrict__ rel_bias,
                bf16* __restrict__ out) {
    extern __shared__ char smc[];
    bf16*  Ks  = (bf16*)smc;             // [256][40]
    bf16*  Vt  = (bf16*)(smc + 20480);   // [32][264]
    bf16*  Ps  = (bf16*)(smc + 37376);   // [256][40]  (Q staging, then P)
    float* bsh = (float*)(smc + 57856);  // [1575]
    int*   sid = (int*)(smc + 64160);    // [256]

    int head = blockIdx.x, win = blockIdx.y;
    int tid = threadIdx.x, lane = tid & 31, warp = tid >> 5;
    int q = lane & 3, g8 = lane >> 2;
    int m0 = warp << 5;

    const bf16* base = qkv + (size_t)win * 256 * 576 + head * HD;
    for (int idx = tid; idx < 256 * 32; idx += 256) {
        int r = idx >> 5, d = idx & 31;
        const bf16* p = base + (size_t)r * 576 + d;
        Ks[r * 40 + d]  = p[192];
        Vt[d * 264 + r] = p[384];
    }
#pragma unroll 4
    for (int i = 0; i < 32; i++)
        Ps[(m0 + i) * 40 + lane] = base[(size_t)(m0 + i) * 576 + lane];
    for (int i = tid; i < 1575; i += 256) bsh[i] = rel_bias[i * 6 + head];
    {
        int t = tid;
        int gd = ((win >> 6) << 2) | (t >> 6);
        int gh = (((win >> 3) & 7) << 3) | ((t >> 3) & 7);
        int gw = ((win & 7) << 3) | (t & 7);
        sid[t] = ((((gd + 2) & 15) >> 2) << 6) | ((((gh + 4) & 63) >> 3) << 3) |
                 (((gw + 4) & 63) >> 3);
    }
    __syncthreads();

    unsigned qf[2][2][4];
#pragma unroll
    for (int mt = 0; mt < 2; mt++)
#pragma unroll
        for (int ks = 0; ks < 2; ks++) {
            int m = m0 + mt * 16 + g8, k = ks * 16 + 2 * q;
            qf[mt][ks][0] = *(const unsigned*)&Ps[m * 40 + k];
            qf[mt][ks][1] = *(const unsigned*)&Ps[(m + 8) * 40 + k];
            qf[mt][ks][2] = *(const unsigned*)&Ps[m * 40 + k + 8];
            qf[mt][ks][3] = *(const unsigned*)&Ps[(m + 8) * 40 + k + 8];
        }
    int rd_[2][2], rh_[2][2], rw_[2][2], msid[2][2];
#pragma unroll
    for (int mt = 0; mt < 2; mt++)
#pragma unroll
        for (int h = 0; h < 2; h++) {
            int r = m0 + mt * 16 + h * 8 + g8;
            rd_[mt][h] = r >> 6; rh_[mt][h] = (r >> 3) & 7; rw_[mt][h] = r & 7;
            msid[mt][h] = sid[r];
        }
    __syncwarp();

    float o[2][4][4];
#pragma unroll
    for (int mt = 0; mt < 2; mt++)
#pragma unroll
        for (int nt = 0; nt < 4; nt++)
#pragma unroll
            for (int e = 0; e < 4; e++) o[mt][nt][e] = 0.f;
    float rs[2][2] = {{0.f, 0.f}, {0.f, 0.f}};

    for (int ck = 0; ck < 256; ck += 32) {
        float s[2][4][4];
#pragma unroll
        for (int mt = 0; mt < 2; mt++)
#pragma unroll
            for (int nt = 0; nt < 4; nt++)
#pragma unroll
                for (int e = 0; e < 4; e++) s[mt][nt][e] = 0.f;
#pragma unroll
        for (int ks = 0; ks < 2; ks++) {
            unsigned kf[4][2];
#pragma unroll
            for (int nt = 0; nt < 4; nt++) {
                int n = ck + nt * 8 + g8;
                kf[nt][0] = *(const unsigned*)&Ks[n * 40 + ks * 16 + 2 * q];
                kf[nt][1] = *(const unsigned*)&Ks[n * 40 + ks * 16 + 2 * q + 8];
            }
#pragma unroll
            for (int mt = 0; mt < 2; mt++)
#pragma unroll
                for (int nt = 0; nt < 4; nt++)
                    MMA_BF16(s[mt][nt], qf[mt][ks], kf[nt]);
        }
#pragma unroll
        for (int nt = 0; nt < 4; nt++) {
            int cc = ck + nt * 8;
            int cd = cc >> 6, ch = (cc >> 3) & 7;
            int sc = (q >= 2) ? sid[cc + 4] : sid[cc];
#pragma unroll
            for (int mt = 0; mt < 2; mt++)
#pragma unroll
                for (int h = 0; h < 2; h++) {
                    int bidx = (rd_[mt][h] - cd + 3) * 225 +
                               (rh_[mt][h] - ch + 7) * 15 + rw_[mt][h] + 7 - (q << 1);
                    float p0, p1;
                    if (msid[mt][h] == sc) {
                        p0 = __expf(fmaf(s[mt][nt][h * 2 + 0], ATTN_SCALE, bsh[bidx]));
                        p1 = __expf(fmaf(s[mt][nt][h * 2 + 1], ATTN_SCALE, bsh[bidx - 1]));
                    } else { p0 = 0.f; p1 = 0.f; }
                    __nv_bfloat162 pp = __floats2bfloat162_rn(p0, p1);
                    rs[mt][h] += __bfloat162float(pp.x) + __bfloat162float(pp.y);
                    int r = m0 + mt * 16 + h * 8 + g8;
                    *(__nv_bfloat162*)&Ps[r * 40 + nt * 8 + (q << 1)] = pp;
                }
        }
        __syncwarp();
#pragma unroll
        for (int ks = 0; ks < 2; ks++) {
            unsigned vf[4][2], pf[2][4];
#pragma unroll
            for (int nto = 0; nto < 4; nto++) {
                int d = nto * 8 + g8;
                vf[nto][0] = *(const unsigned*)&Vt[d * 264 + ck + ks * 16 + 2 * q];
                vf[nto][1] = *(const unsigned*)&Vt[d * 264 + ck + ks * 16 + 2 * q + 8];
            }
#pragma unroll
            for (int mt = 0; mt < 2; mt++) {
                int m = m0 + mt * 16 + g8, k = ks * 16 + 2 * q;
                pf[mt][0] = *(const unsigned*)&Ps[m * 40 + k];
                pf[mt][1] = *(const unsigned*)&Ps[(m + 8) * 40 + k];
                pf[mt][2] = *(const unsigned*)&Ps[m * 40 + k + 8];
                pf[mt][3] = *(const unsigned*)&Ps[(m + 8) * 40 + k + 8];
            }
#pragma unroll
            for (int mt = 0; mt < 2; mt++)
#pragma unroll
                for (int nto = 0; nto < 4; nto++)
                    MMA_BF16(o[mt][nto], pf[mt], vf[nto]);
        }
        __syncwarp();
    }

#pragma unroll
    for (int mt = 0; mt < 2; mt++)
#pragma unroll
        for (int h = 0; h < 2; h++) {
            float v = rs[mt][h];
            v += __shfl_xor_sync(0xffffffffu, v, 1);
            v += __shfl_xor_sync(0xffffffffu, v, 2);
            rs[mt][h] = 1.f / v;
        }
#pragma unroll
    for (int mt = 0; mt < 2; mt++)
#pragma unroll
        for (int h = 0; h < 2; h++) {
            int r = m0 + mt * 16 + h * 8 + g8;
            bf16* op = out + (size_t)(win * 256 + r) * CDIM + head * HD;
            float inv = rs[mt][h];
#pragma unroll
            for (int nto = 0; nto < 4; nto++)
                *(__nv_bfloat162*)(op + nto * 8 + (q << 1)) =
                    __floats2bfloat162_rn(o[mt][nto][h * 2 + 0] * inv,
                                          o[mt][nto][h * 2 + 1] * inv);
        }
}

// ---------------- tiled depthwise 3x3x3 conv + bias + exact GELU -------------------
#define CONV_SMEM_BYTES (216 * 128 * 2)
__global__ void __launch_bounds__(256)
conv_gelu_tiled(const bf16* __restrict__ hin, const float* __restrict__ wt,
                const float* __restrict__ cb, bf16* __restrict__ hout) {
    extern __shared__ bf16 hs[];   // [216][128]
    int cg = blockIdx.x;
    int tile = blockIdx.y;
    int d0 = (tile >> 8) << 2;
    int h0 = ((tile >> 4) & 15) << 2;
    int w0 = (tile & 15) << 2;
    int tid = threadIdx.x;
    int c = tid & 127;
    int phalf = tid >> 7;
    int cbase = cg << 7;

#pragma unroll 4
    for (int i = 0; i < 108; i++) {
        int p = phalf + (i << 1);
        int pd = p / 36, rem = p - pd * 36;
        int ph = rem / 6, pw = rem - ph * 6;
        int gd = d0 - 1 + pd, gh = h0 - 1 + ph, gw = w0 - 1 + pw;
        bf16 v = __float2bfloat16(0.f);
        if ((unsigned)gd < 16u && (unsigned)gh < 64u && (unsigned)gw < 64u)
            v = hin[(size_t)((gd << 12) | (gh << 6) | gw) * HIDDEN + cbase + c];
        hs[p * 128 + c] = v;
    }
    float w[27];
#pragma unroll
    for (int k = 0; k < 27; k++) w[k] = wt[(cbase + c) * 27 + k];
    float bias = cb[cbase + c];
    __syncthreads();

#pragma unroll 2
    for (int i = 0; i < 32; i++) {
        int t = phalf + (i << 1);
        int td = t >> 4, th = (t >> 2) & 3, tw = t & 3;
        float acc = bias;
        int k = 0;
#pragma unroll
        for (int kd = 0; kd < 3; kd++)
#pragma unroll
            for (int kh = 0; kh < 3; kh++) {
                int pbase = (td + kd) * 36 + (th + kh) * 6 + tw;
#pragma unroll
                for (int kw = 0; kw < 3; kw++, k++)
                    acc += w[k] * __bfloat162float(hs[(pbase + kw) * 128 + c]);
            }
        float gl = 0.5f * acc * (1.f + erff(acc * 0.70710678118654752f));
        int n = ((d0 + td) << 12) | ((h0 + th) << 6) | (w0 + tw);
        hout[(size_t)n * HIDDEN + cbase + c] = __float2bfloat16(gl);
    }
}

// ---------------- launch ----------------
extern "C" void kernel_launch(void* const* d_in, const int* in_sizes, int n_in,
                              void* d_out, int out_size) {
    const float* x     = (const float*)d_in[0];
    const float* n1g   = (const float*)d_in[1];
    const float* n1b   = (const float*)d_in[2];
    const float* qkvw  = (const float*)d_in[3];
    const float* qkvb  = (const float*)d_in[4];
    const float* relb  = (const float*)d_in[5];
    const float* projw = (const float*)d_in[6];
    const float* projb = (const float*)d_in[7];
    const float* n2g   = (const float*)d_in[8];
    const float* n2b   = (const float*)d_in[9];
    const float* fc1A  = (const float*)d_in[10];
    const float* fc1Bw = (const float*)d_in[11];
    const float* fc1Bb = (const float*)d_in[12];
    const float* dww   = (const float*)d_in[13];
    const float* dwb   = (const float*)d_in[14];
    const float* fc2A  = (const float*)d_in[15];
    const float* fc2Bw = (const float*)d_in[16];
    const float* fc2Bb = (const float*)d_in[17];
    float* out = (float*)d_out;

    bf16 *p_ln, *p_qkv, *p_attn, *p_r1, *p_hid, *p_conv, *p_r2;
    bf16 *p_qkvwt, *p_projwt, *p_fc1At, *p_fc1Bt, *p_fc2At, *p_fc2Bt;
    float *p_x1;
    cudaGetSymbolAddress((void**)&p_ln,    g_ln);
    cudaGetSymbolAddress((void**)&p_qkv,   g_qkv);
    cudaGetSymbolAddress((void**)&p_attn,  g_attn);
    cudaGetSymbolAddress((void**)&p_x1,    g_x1);
    cudaGetSymbolAddress((void**)&p_r1,    g_r1);
    cudaGetSymbolAddress((void**)&p_hid,   g_hid);
    cudaGetSymbolAddress((void**)&p_conv,  g_conv);
    cudaGetSymbolAddress((void**)&p_r2,    g_r2);
    cudaGetSymbolAddress((void**)&p_qkvwt, g_qkvwt);
    cudaGetSymbolAddress((void**)&p_projwt, g_projwt);
    cudaGetSymbolAddress((void**)&p_fc1At, g_fc1At);
    cudaGetSymbolAddress((void**)&p_fc1Bt, g_fc1Bt);
    cudaGetSymbolAddress((void**)&p_fc2At, g_fc2At);
    cudaGetSymbolAddress((void**)&p_fc2Bt, g_fc2Bt);

    cudaFuncSetAttribute(attn_mma_kernel, cudaFuncAttributeMaxDynamicSharedMemorySize,
                         ATTN_SMEM_BYTES);
    cudaFuncSetAttribute(conv_gelu_tiled, cudaFuncAttributeMaxDynamicSharedMemorySize,
                         CONV_SMEM_BYTES);
    cudaFuncSetAttribute(mma_gemm<0, true>,  cudaFuncAttributeMaxDynamicSharedMemorySize, GEMM_SMEM_BYTES);
    cudaFuncSetAttribute(mma_gemm<1, true>,  cudaFuncAttributeMaxDynamicSharedMemorySize, GEMM_SMEM_BYTES);
    cudaFuncSetAttribute(mma_gemm<2, false>, cudaFuncAttributeMaxDynamicSharedMemorySize, GEMM_SMEM_BYTES);
    cudaFuncSetAttribute(mma_gemm<3, false>, cudaFuncAttributeMaxDynamicSharedMemorySize, GEMM_SMEM_BYTES);

    // 0. all weights convert+transpose (one launch)
    wconv_all<<<(638976 + 255) / 256, 256>>>(qkvw, projw, fc1A, fc1Bw, fc2A, fc2Bw,
                                             p_qkvwt, p_projwt, p_fc1At, p_fc1Bt,
                                             p_fc2At, p_fc2Bt);

    // 1. LN1 + window permute (bf16 out)
    ln_kernel<true><<<NTOK / 8, 256>>>(x, n1g, n1b, p_ln);
    // 2. qkv = xw @ qkv_w + b   [65536 x 576], K=192  (bf16 out)
    mma_gemm<1, true><<<dim3(5, 512), 256, GEMM_SMEM_BYTES>>>(p_ln, p_qkvwt, qkvb, nullptr, p_qkv, 576, 192);
    // 3. windowed attention (bf16)
    attn_mma_kernel<<<dim3(NHEADS, 256), 256, ATTN_SMEM_BYTES>>>(p_qkv, relb, p_attn);
    // 4. proj + inverse permute + residual -> x1 fp32
    mma_gemm<2, false><<<dim3(2, 512), 256, GEMM_SMEM_BYTES>>>(p_attn, p_projwt, projb, x, p_x1, 192, 192);
    // 5. LN2 (bf16 out)
    ln_kernel<false><<<NTOK / 8, 256>>>(p_x1, n2g, n2b, p_ln);
    // 6. r1 = hn @ fc1_A   [65536 x 384], K=192 (bf16)
    mma_gemm<0, true><<<dim3(3, 512), 256, GEMM_SMEM_BYTES>>>(p_ln, p_fc1At, nullptr, nullptr, p_r1, 384, 192);
    // 7. hid = r1 @ fc1_Bw + b   [65536 x 768], K=384 (bf16)
    mma_gemm<1, true><<<dim3(6, 512), 256, GEMM_SMEM_BYTES>>>(p_r1, p_fc1Bt, fc1Bb, nullptr, p_hid, 768, 384);
    // 8. tiled depthwise conv3d + bias + GELU (bf16)
    conv_gelu_tiled<<<dim3(6, 1024), 256, CONV_SMEM_BYTES>>>(p_hid, dww, dwb, p_conv);
    // 9. r2 = conv @ fc2_A   [65536 x 128(pad)], K=768 (bf16)
    mma_gemm<0, true><<<dim3(1, 512), 256, GEMM_SMEM_BYTES>>>(p_conv, p_fc2At, nullptr, nullptr, p_r2, 128, 768);
    // 10. out = x1 + r2 @ fc2_Bw + b   [65536 x 192], K=128(pad) (fp32)
    mma_gemm<3, false><<<dim3(2, 512), 256, GEMM_SMEM_BYTES>>>(p_r2, p_fc2Bt, fc2Bb, p_x1, out, 192, 128);
}